// round 3
// baseline (speedup 1.0000x reference)
#include <cuda_runtime.h>
#include <cuda_bf16.h>
#include <math.h>

#define Tn   2048
#define Cn   2048
#define ATTn 512

// scratch (device globals are zero-initialized; +2 row padding for scan prefetch)
__device__ float g_r[Tn*Cn];
__device__ float g_k[Tn*ATTn];
__device__ float g_v[Tn*ATTn];
__device__ float g_wcat[Cn*512];
__device__ float g_h1[Tn*512];
__device__ float g_wdec[(Tn+2)*Cn];
__device__ float g_iclr[(Tn+2)*Cn];
__device__ float g_vsig[Tn*Cn];
__device__ float g_gate[Tn*Cn];
__device__ float g_rrot[(Tn+2)*Cn];
__device__ float g_kfin[(Tn+2)*Cn];
__device__ float g_vfin[(Tn+2)*Cn];
__device__ float g_kk  [(Tn+2)*Cn];
__device__ float g_y[Tn*Cn];
__device__ float g_z[Tn*Cn];

__device__ __forceinline__ float sigf(float x){ return 1.0f/(1.0f + expf(-x)); }
__device__ __forceinline__ float decay_fn(float v){
    float nv = -v;
    float sp = (nv > 20.0f) ? nv : log1pf(expf(nv));
    return expf(-expf(-sp - 0.5f));
}

// C[M,N] = A[M,K] @ B[N,K]^T + bias, 128x128 tile
__global__ __launch_bounds__(256) void gemm_nt128(
    const float* __restrict__ A, const float* __restrict__ B,
    const float* __restrict__ bias, float* __restrict__ C, int N, int K)
{
    __shared__ float As[8][128], Bs[8][128];
    const int m0 = blockIdx.y*128, n0 = blockIdx.x*128;
    const int tid = threadIdx.x, tx = tid & 15, ty = tid >> 4;
    const int lr = tid >> 1, lk = (tid & 1)*4;
    const float* Ap = A + (size_t)(m0+lr)*K + lk;
    const float* Bp = B + (size_t)(n0+lr)*K + lk;
    float acc[8][8];
    #pragma unroll
    for (int i=0;i<8;i++){
        #pragma unroll
        for (int j=0;j<8;j++) acc[i][j]=0.f;
    }
    for (int kt=0; kt<K; kt+=8){
        float4 av = *(const float4*)(Ap + kt);
        float4 bv = *(const float4*)(Bp + kt);
        __syncthreads();
        As[lk+0][lr]=av.x; As[lk+1][lr]=av.y; As[lk+2][lr]=av.z; As[lk+3][lr]=av.w;
        Bs[lk+0][lr]=bv.x; Bs[lk+1][lr]=bv.y; Bs[lk+2][lr]=bv.z; Bs[lk+3][lr]=bv.w;
        __syncthreads();
        #pragma unroll
        for (int k=0;k<8;k++){
            float4 a0 = *(const float4*)&As[k][ty*4];
            float4 a1 = *(const float4*)&As[k][64+ty*4];
            float4 b0 = *(const float4*)&Bs[k][tx*4];
            float4 b1 = *(const float4*)&Bs[k][64+tx*4];
            float a[8]={a0.x,a0.y,a0.z,a0.w,a1.x,a1.y,a1.z,a1.w};
            float b[8]={b0.x,b0.y,b0.z,b0.w,b1.x,b1.y,b1.z,b1.w};
            #pragma unroll
            for (int i=0;i<8;i++){
                #pragma unroll
                for (int j=0;j<8;j++) acc[i][j]=fmaf(a[i],b[j],acc[i][j]);
            }
        }
    }
    float b0v[4]={0,0,0,0}, b1v[4]={0,0,0,0};
    if (bias){
        #pragma unroll
        for (int j=0;j<4;j++){ b0v[j]=bias[n0+tx*4+j]; b1v[j]=bias[n0+64+tx*4+j]; }
    }
    #pragma unroll
    for (int ii=0; ii<8; ii++){
        int gm = m0 + ((ii<4)? (ty*4+ii) : (64+ty*4+ii-4));
        *(float4*)(C + (size_t)gm*N + n0+tx*4) =
            make_float4(acc[ii][0]+b0v[0],acc[ii][1]+b0v[1],acc[ii][2]+b0v[2],acc[ii][3]+b0v[3]);
        *(float4*)(C + (size_t)gm*N + n0+64+tx*4) =
            make_float4(acc[ii][4]+b1v[0],acc[ii][5]+b1v[1],acc[ii][6]+b1v[2],acc[ii][7]+b1v[3]);
    }
}

// C[M,N] = A[M,K] @ B[N,K]^T + bias, 64x64 tile
__global__ __launch_bounds__(256) void gemm_nt64(
    const float* __restrict__ A, const float* __restrict__ B,
    const float* __restrict__ bias, float* __restrict__ C, int N, int K)
{
    __shared__ float As[16][64], Bs[16][64];
    const int m0 = blockIdx.y*64, n0 = blockIdx.x*64;
    const int tid = threadIdx.x, tx = tid & 15, ty = tid >> 4;
    const int lr = tid >> 2, lk = (tid & 3)*4;
    const float* Ap = A + (size_t)(m0+lr)*K + lk;
    const float* Bp = B + (size_t)(n0+lr)*K + lk;
    float acc[4][4];
    #pragma unroll
    for (int i=0;i<4;i++){
        #pragma unroll
        for (int j=0;j<4;j++) acc[i][j]=0.f;
    }
    for (int kt=0; kt<K; kt+=16){
        float4 av = *(const float4*)(Ap + kt);
        float4 bv = *(const float4*)(Bp + kt);
        __syncthreads();
        As[lk+0][lr]=av.x; As[lk+1][lr]=av.y; As[lk+2][lr]=av.z; As[lk+3][lr]=av.w;
        Bs[lk+0][lr]=bv.x; Bs[lk+1][lr]=bv.y; Bs[lk+2][lr]=bv.z; Bs[lk+3][lr]=bv.w;
        __syncthreads();
        #pragma unroll
        for (int k=0;k<16;k++){
            float4 a4 = *(const float4*)&As[k][ty*4];
            float4 b4 = *(const float4*)&Bs[k][tx*4];
            float a[4]={a4.x,a4.y,a4.z,a4.w}, b[4]={b4.x,b4.y,b4.z,b4.w};
            #pragma unroll
            for (int i=0;i<4;i++){
                #pragma unroll
                for (int j=0;j<4;j++) acc[i][j]=fmaf(a[i],b[j],acc[i][j]);
            }
        }
    }
    float bb[4]={0,0,0,0};
    if (bias){
        #pragma unroll
        for (int j=0;j<4;j++) bb[j]=bias[n0+tx*4+j];
    }
    #pragma unroll
    for (int ii=0; ii<4; ii++){
        int gm = m0 + ty*4 + ii;
        *(float4*)(C + (size_t)gm*N + n0+tx*4) =
            make_float4(acc[ii][0]+bb[0],acc[ii][1]+bb[1],acc[ii][2]+bb[2],acc[ii][3]+bb[3]);
    }
}

// C[M,N] = actA(A[M,K]) @ B[K,N]; epi: 0 none, 3 sigmoid(c+bias), 4 decay(c+bias)
// actA: 0 none, 1 tanh, 2 sigmoid
__global__ __launch_bounds__(256) void gemm_nn64(
    const float* __restrict__ A, int lda, const float* __restrict__ B, int ldb,
    const float* __restrict__ bias, float* __restrict__ C, int ldc,
    int N, int K, int actA, int epi)
{
    __shared__ float As[16][64], Bs[16][64];
    const int m0 = blockIdx.y*64, n0 = blockIdx.x*64;
    const int tid = threadIdx.x, tx = tid & 15, ty = tid >> 4;
    const int alr = tid >> 2, alk = (tid & 3)*4;
    const int bkr = tid >> 4, bnq = (tid & 15)*4;
    float acc[4][4];
    #pragma unroll
    for (int i=0;i<4;i++){
        #pragma unroll
        for (int j=0;j<4;j++) acc[i][j]=0.f;
    }
    for (int kt=0; kt<K; kt+=16){
        float4 av = *(const float4*)(A + (size_t)(m0+alr)*lda + kt + alk);
        float4 bv = *(const float4*)(B + (size_t)(kt+bkr)*ldb + n0 + bnq);
        if (actA==1){ av.x=tanhf(av.x); av.y=tanhf(av.y); av.z=tanhf(av.z); av.w=tanhf(av.w); }
        else if (actA==2){ av.x=sigf(av.x); av.y=sigf(av.y); av.z=sigf(av.z); av.w=sigf(av.w); }
        __syncthreads();
        As[alk+0][alr]=av.x; As[alk+1][alr]=av.y; As[alk+2][alr]=av.z; As[alk+3][alr]=av.w;
        *(float4*)&Bs[bkr][bnq] = bv;
        __syncthreads();
        #pragma unroll
        for (int k=0;k<16;k++){
            float4 a4 = *(const float4*)&As[k][ty*4];
            float4 b4 = *(const float4*)&Bs[k][tx*4];
            float a[4]={a4.x,a4.y,a4.z,a4.w}, b[4]={b4.x,b4.y,b4.z,b4.w};
            #pragma unroll
            for (int i=0;i<4;i++){
                #pragma unroll
                for (int j=0;j<4;j++) acc[i][j]=fmaf(a[i],b[j],acc[i][j]);
            }
        }
    }
    const int n = n0 + tx*4;
    float bb[4]={0,0,0,0};
    if (bias){
        #pragma unroll
        for (int j=0;j<4;j++) bb[j]=bias[n+j];
    }
    #pragma unroll
    for (int ii=0; ii<4; ii++){
        int gm = m0 + ty*4 + ii;
        float o[4];
        #pragma unroll
        for (int j=0;j<4;j++){
            float c = acc[ii][j];
            if (epi==3)      c = sigf(c + bb[j]);
            else if (epi==4) c = decay_fn(c + bb[j]);
            o[j]=c;
        }
        *(float4*)(C + (size_t)gm*ldc + n) = make_float4(o[0],o[1],o[2],o[3]);
    }
}

__global__ void pack_w(const float* __restrict__ w1, const float* __restrict__ a1,
                       const float* __restrict__ v1, const float* __restrict__ g1,
                       float* __restrict__ out)
{
    int k = blockIdx.x, c = threadIdx.x;
    float val;
    if      (c < 96)  val = w1[k*96  + c];
    else if (c < 192) val = a1[k*96  + (c-96)];
    else if (c < 256) val = v1[k*64  + (c-192)];
    else              val = g1[k*256 + (c-256)];
    out[k*512 + c] = val;
}

// rope r/k, GQA repeat, kk normalize, k_final, v_final
__global__ __launch_bounds__(256) void prep_kernel(
    const float* __restrict__ rbuf, const float* __restrict__ kbuf, const float* __restrict__ vbuf,
    const float* __restrict__ iclr, const float* __restrict__ vsig, const float* __restrict__ vfirst,
    const float* __restrict__ cosb, const float* __restrict__ sinb,
    const float* __restrict__ k_k, const float* __restrict__ k_a,
    float* __restrict__ rrot, float* __restrict__ kkout,
    float* __restrict__ kfin, float* __restrict__ vfin)
{
    int wid = (blockIdx.x*blockDim.x + threadIdx.x) >> 5;
    int l = threadIdx.x & 31;
    int t = wid >> 5, h = wid & 31;
    int d0 = l, d1 = l+32;
    float c0 = cosb[t*64+d0], c1 = cosb[t*64+d1];
    float s0 = sinb[t*64+d0], s1 = sinb[t*64+d1];
    int base = t*Cn + h*64;
    float r0 = rbuf[base+d0], r1 = rbuf[base+d1];
    rrot[base+d0] = r0*c0 - r1*s0;
    rrot[base+d1] = r1*c1 + r0*s1;
    int kbase = t*ATTn + (h>>2)*64;
    float k0 = kbuf[kbase+d0], k1 = kbuf[kbase+d1];
    float kr0 = k0*c0 - k1*s0, kr1 = k1*c1 + k0*s1;
    float m0 = kr0 * k_k[h*64+d0], m1 = kr1 * k_k[h*64+d1];
    float ss = m0*m0 + m1*m1;
    #pragma unroll
    for (int o=16;o>0;o>>=1) ss += __shfl_xor_sync(0xffffffffu, ss, o);
    float inv = 1.0f / fmaxf(sqrtf(ss), 1e-12f);
    kkout[base+d0] = m0*inv; kkout[base+d1] = m1*inv;
    float ic0 = iclr[base+d0], ic1 = iclr[base+d1];
    kfin[base+d0] = kr0 * (1.0f + (ic0-1.0f)*k_a[h*64+d0]);
    kfin[base+d1] = kr1 * (1.0f + (ic1-1.0f)*k_a[h*64+d1]);
    float v0v = vbuf[kbase+d0], v1v = vbuf[kbase+d1];
    vfin[base+d0] = v0v + (vfirst[base+d0]-v0v)*vsig[base+d0];
    vfin[base+d1] = v1v + (vfirst[base+d1]-v1v)*vsig[base+d1];
}

// sequential scan: 128 CTAs = 4 per head; 16 rows x 8 lanes; S in registers
__global__ __launch_bounds__(128) void scan_kernel(
    const float* __restrict__ wdec, const float* __restrict__ kkb,
    const float* __restrict__ aic,  const float* __restrict__ kf,
    const float* __restrict__ vf,   const float* __restrict__ rr,
    const float* __restrict__ s_in, float* __restrict__ yout, float* __restrict__ s_out)
{
    const int b = blockIdx.x, h = b >> 2, rbk = b & 3;
    const int tid = threadIdx.x, rl = tid >> 3, sub = tid & 7;
    const int i = rbk*16 + rl, cb = sub*8;
    const int coff = h*64 + cb, voff = h*64 + i;

    float S[8];
    { const float4* sp = (const float4*)(s_in + (size_t)(h*64 + i)*64 + cb);
      float4 a = sp[0], c = sp[1];
      S[0]=a.x;S[1]=a.y;S[2]=a.z;S[3]=a.w;S[4]=c.x;S[5]=c.y;S[6]=c.z;S[7]=c.w; }

    float4 Bw[2][2], Bk[2][2], Ba[2][2], Bf[2][2], Br[2][2];
    float Bv[2];
    #pragma unroll
    for (int p=0;p<2;p++){
        size_t t0 = (size_t)p*Cn;
        Bw[p][0]=((const float4*)(wdec+t0+coff))[0]; Bw[p][1]=((const float4*)(wdec+t0+coff))[1];
        Bk[p][0]=((const float4*)(kkb +t0+coff))[0]; Bk[p][1]=((const float4*)(kkb +t0+coff))[1];
        Ba[p][0]=((const float4*)(aic +t0+coff))[0]; Ba[p][1]=((const float4*)(aic +t0+coff))[1];
        Bf[p][0]=((const float4*)(kf  +t0+coff))[0]; Bf[p][1]=((const float4*)(kf  +t0+coff))[1];
        Br[p][0]=((const float4*)(rr  +t0+coff))[0]; Br[p][1]=((const float4*)(rr  +t0+coff))[1];
        Bv[p] = vf[t0 + voff];
    }

    #pragma unroll 2
    for (int t=0; t<Tn; t++){
        const int p = t & 1;
        float w[8], kv[8], av[8], fv[8], rv[8];
        { float4 x0=Bw[p][0], x1=Bw[p][1]; w[0]=x0.x;w[1]=x0.y;w[2]=x0.z;w[3]=x0.w;w[4]=x1.x;w[5]=x1.y;w[6]=x1.z;w[7]=x1.w; }
        { float4 x0=Bk[p][0], x1=Bk[p][1]; kv[0]=x0.x;kv[1]=x0.y;kv[2]=x0.z;kv[3]=x0.w;kv[4]=x1.x;kv[5]=x1.y;kv[6]=x1.z;kv[7]=x1.w; }
        { float4 x0=Ba[p][0], x1=Ba[p][1]; av[0]=x0.x;av[1]=x0.y;av[2]=x0.z;av[3]=x0.w;av[4]=x1.x;av[5]=x1.y;av[6]=x1.z;av[7]=x1.w; }
        { float4 x0=Bf[p][0], x1=Bf[p][1]; fv[0]=x0.x;fv[1]=x0.y;fv[2]=x0.z;fv[3]=x0.w;fv[4]=x1.x;fv[5]=x1.y;fv[6]=x1.z;fv[7]=x1.w; }
        { float4 x0=Br[p][0], x1=Br[p][1]; rv[0]=x0.x;rv[1]=x0.y;rv[2]=x0.z;rv[3]=x0.w;rv[4]=x1.x;rv[5]=x1.y;rv[6]=x1.z;rv[7]=x1.w; }
        float vi = Bv[p];
        { // prefetch t+2
            const size_t t2 = (size_t)(t + 2)*Cn;
            Bw[p][0]=((const float4*)(wdec+t2+coff))[0]; Bw[p][1]=((const float4*)(wdec+t2+coff))[1];
            Bk[p][0]=((const float4*)(kkb +t2+coff))[0]; Bk[p][1]=((const float4*)(kkb +t2+coff))[1];
            Ba[p][0]=((const float4*)(aic +t2+coff))[0]; Ba[p][1]=((const float4*)(aic +t2+coff))[1];
            Bf[p][0]=((const float4*)(kf  +t2+coff))[0]; Bf[p][1]=((const float4*)(kf  +t2+coff))[1];
            Br[p][0]=((const float4*)(rr  +t2+coff))[0]; Br[p][1]=((const float4*)(rr  +t2+coff))[1];
            Bv[p] = vf[t2 + voff];
        }
        float sd0=0.f, sd1=0.f;
        #pragma unroll
        for (int q=0;q<4;q++){ sd0 = fmaf(S[q],kv[q],sd0); sd1 = fmaf(S[q+4],kv[q+4],sd1); }
        float sd = sd0 + sd1;
        sd += __shfl_xor_sync(0xffffffffu, sd, 1);
        sd += __shfl_xor_sync(0xffffffffu, sd, 2);
        sd += __shfl_xor_sync(0xffffffffu, sd, 4);
        float y0=0.f, y1=0.f;
        #pragma unroll
        for (int q=0;q<8;q++){
            float ab  = kv[q]*av[q];
            float tmp = fmaf(S[q], w[q], vi*fv[q]);
            S[q] = fmaf(-sd, ab, tmp);
            if (q<4) y0 = fmaf(S[q], rv[q], y0); else y1 = fmaf(S[q], rv[q], y1);
        }
        float yv = y0+y1;
        yv += __shfl_xor_sync(0xffffffffu, yv, 1);
        yv += __shfl_xor_sync(0xffffffffu, yv, 2);
        yv += __shfl_xor_sync(0xffffffffu, yv, 4);
        if (sub==0) yout[(size_t)t*Cn + voff] = yv;
    }
    float4* so = (float4*)(s_out + (size_t)(h*64+i)*64 + cb);
    so[0] = make_float4(S[0],S[1],S[2],S[3]);
    so[1] = make_float4(S[4],S[5],S[6],S[7]);
}

// groupnorm + ln + bonus + gate
__global__ __launch_bounds__(256) void post_kernel(
    const float* __restrict__ y, const float* __restrict__ rrot,
    const float* __restrict__ kfin, const float* __restrict__ vfin,
    const float* __restrict__ gate, const float* __restrict__ r_k,
    const float* __restrict__ ln_w, const float* __restrict__ ln_b,
    float* __restrict__ z)
{
    int wid = (blockIdx.x*blockDim.x + threadIdx.x) >> 5;
    int l = threadIdx.x & 31;
    int t = wid >> 5, h = wid & 31;
    int base = t*Cn + h*64;
    int d0 = l, d1 = l+32;
    float y0 = y[base+d0], y1 = y[base+d1];
    float s = y0+y1, sq = y0*y0 + y1*y1;
    float r0 = rrot[base+d0], r1 = rrot[base+d1];
    float dot = r0*kfin[base+d0]*r_k[h*64+d0] + r1*kfin[base+d1]*r_k[h*64+d1];
    #pragma unroll
    for (int o=16;o>0;o>>=1){
        s   += __shfl_xor_sync(0xffffffffu, s, o);
        sq  += __shfl_xor_sync(0xffffffffu, sq, o);
        dot += __shfl_xor_sync(0xffffffffu, dot, o);
    }
    float mu = s * (1.0f/64.0f);
    float var = sq * (1.0f/64.0f) - mu*mu;
    float rstd = rsqrtf(var + 6.4e-4f);
    float n0 = (y0-mu)*rstd*ln_w[h*64+d0] + ln_b[h*64+d0];
    float n1 = (y1-mu)*rstd*ln_w[h*64+d1] + ln_b[h*64+d1];
    z[base+d0] = (n0 + dot*vfin[base+d0]) * gate[base+d0];
    z[base+d1] = (n1 + dot*vfin[base+d1]) * gate[base+d1];
}

extern "C" void kernel_launch(void* const* d_in, const int* in_sizes, int n_in,
                              void* d_out, int out_size) {
    const float* x       = (const float*)d_in[0];
    const float* wkv_in  = (const float*)d_in[1];
    const float* v_first = (const float*)d_in[2];
    const float* cosb    = (const float*)d_in[3];
    const float* sinb    = (const float*)d_in[4];
    const float* w0      = (const float*)d_in[5];
    const float* w1      = (const float*)d_in[6];
    const float* w2      = (const float*)d_in[7];
    const float* a0      = (const float*)d_in[8];
    const float* a1      = (const float*)d_in[9];
    const float* a2      = (const float*)d_in[10];
    const float* v0      = (const float*)d_in[11];
    const float* v1      = (const float*)d_in[12];
    const float* v2      = (const float*)d_in[13];
    const float* g1      = (const float*)d_in[14];
    const float* g2      = (const float*)d_in[15];
    const float* k_k     = (const float*)d_in[16];
    const float* k_a     = (const float*)d_in[17];
    const float* r_k     = (const float*)d_in[18];
    const float* q_w     = (const float*)d_in[19];
    const float* q_b     = (const float*)d_in[20];
    const float* k_w     = (const float*)d_in[21];
    const float* k_b     = (const float*)d_in[22];
    const float* v_w     = (const float*)d_in[23];
    const float* v_b     = (const float*)d_in[24];
    const float* o_w     = (const float*)d_in[25];
    const float* ln_w    = (const float*)d_in[26];
    const float* ln_b    = (const float*)d_in[27];

    float* out   = (float*)d_out;
    float* s_out = out + (size_t)Tn*Cn;
    float* vf_out = s_out + 32*64*64;

    float *p_r, *p_k, *p_v, *p_wcat, *p_h1, *p_wdec, *p_iclr, *p_vsig, *p_gate;
    float *p_rrot, *p_kfin, *p_vfin, *p_kk, *p_y, *p_z;
    cudaGetSymbolAddress((void**)&p_r, g_r);
    cudaGetSymbolAddress((void**)&p_k, g_k);
    cudaGetSymbolAddress((void**)&p_v, g_v);
    cudaGetSymbolAddress((void**)&p_wcat, g_wcat);
    cudaGetSymbolAddress((void**)&p_h1, g_h1);
    cudaGetSymbolAddress((void**)&p_wdec, g_wdec);
    cudaGetSymbolAddress((void**)&p_iclr, g_iclr);
    cudaGetSymbolAddress((void**)&p_vsig, g_vsig);
    cudaGetSymbolAddress((void**)&p_gate, g_gate);
    cudaGetSymbolAddress((void**)&p_rrot, g_rrot);
    cudaGetSymbolAddress((void**)&p_kfin, g_kfin);
    cudaGetSymbolAddress((void**)&p_vfin, g_vfin);
    cudaGetSymbolAddress((void**)&p_kk, g_kk);
    cudaGetSymbolAddress((void**)&p_y, g_y);
    cudaGetSymbolAddress((void**)&p_z, g_z);

    gemm_nt128<<<dim3(16,16),256>>>(x, q_w, q_b, p_r, Cn, Cn);
    gemm_nt64 <<<dim3(8,32),256>>>(x, k_w, k_b, p_k, ATTn, Cn);
    gemm_nt64 <<<dim3(8,32),256>>>(x, v_w, v_b, p_v, ATTn, Cn);
    pack_w    <<<Cn,512>>>(w1, a1, v1, g1, p_wcat);
    gemm_nn64 <<<dim3(8,32),256>>>(x, Cn, p_wcat, 512, nullptr, p_h1, 512, 512, Cn, 0, 0);
    gemm_nn64 <<<dim3(32,32),256>>>(p_h1+0,   512, w2, Cn, w0,      p_wdec, Cn, Cn,  96, 1, 4);
    gemm_nn64 <<<dim3(32,32),256>>>(p_h1+96,  512, a2, Cn, a0,      p_iclr, Cn, Cn,  96, 0, 3);
    gemm_nn64 <<<dim3(32,32),256>>>(p_h1+192, 512, v2, Cn, v0,      p_vsig, Cn, Cn,  64, 0, 3);
    gemm_nn64 <<<dim3(32,32),256>>>(p_h1+256, 512, g2, Cn, nullptr, p_gate, Cn, Cn, 256, 2, 0);
    prep_kernel<<<8192,256>>>(p_r, p_k, p_v, p_iclr, p_vsig, v_first, cosb, sinb,
                              k_k, k_a, p_rrot, p_kk, p_kfin, p_vfin);
    scan_kernel<<<128,128>>>(p_wdec, p_kk, p_iclr, p_kfin, p_vfin, p_rrot,
                             wkv_in, p_y, s_out);
    post_kernel<<<8192,256>>>(p_y, p_rrot, p_kfin, p_vfin, p_gate, r_k, ln_w, ln_b, p_z);
    gemm_nt128<<<dim3(16,16),256>>>(p_z, o_w, nullptr, out, Cn, Cn);
    cudaMemcpyAsync(vf_out, v_first, (size_t)Tn*Cn*sizeof(float),
                    cudaMemcpyDeviceToDevice, 0);
}

// round 4
// speedup vs baseline: 1.3820x; 1.3820x over previous
#include <cuda_runtime.h>
#include <cuda_bf16.h>
#include <math.h>

#define Tn   2048
#define Cn   2048
#define ATTn 512

// scratch (device globals are zero-initialized; +2 row padding for scan prefetch)
__device__ float g_r[Tn*Cn];
__device__ float g_k[Tn*ATTn];
__device__ float g_v[Tn*ATTn];
__device__ float g_wcatT[512*Cn];          // transposed pack: [512][2048]
__device__ float g_h1[Tn*512];
__device__ float g_wdec[(Tn+2)*Cn];
__device__ float g_iclr[(Tn+2)*Cn];
__device__ float g_vsig[Tn*Cn];
__device__ float g_gate[Tn*Cn];
__device__ float g_rrot[(Tn+2)*Cn];
__device__ float g_kfin[(Tn+2)*Cn];
__device__ float g_vfin[(Tn+2)*Cn];
__device__ float g_kk  [(Tn+2)*Cn];
__device__ float g_y[Tn*Cn];
__device__ float g_z[Tn*Cn];

__device__ __forceinline__ float sigf(float x){ return 1.0f/(1.0f + expf(-x)); }
__device__ __forceinline__ float decay_fn(float v){
    float nv = -v;
    float sp = (nv > 20.0f) ? nv : log1pf(expf(nv));
    return expf(-expf(-sp - 0.5f));
}
__device__ __forceinline__ unsigned f2tf32(float f){
    unsigned u;
    asm("cvt.rna.tf32.f32 %0, %1;" : "=r"(u) : "f"(f));
    return u;
}

// ---------------- TF32 tensor-core GEMM: C[M,N] = A[M,K] @ B[N,K]^T + bias ----------------
// 128x128x32 tile, 256 threads = 8 warps (4x2), warp tile 32x64 (2x8 m16n8k8 mmas)
#define BM 128
#define BN 128
#define BK 32
#define SPAD 36

__global__ __launch_bounds__(256) void gemm_nt_tf32(
    const float* __restrict__ A, const float* __restrict__ B,
    const float* __restrict__ bias, float* __restrict__ C, int N, int K)
{
    __shared__ unsigned As[BM*SPAD];
    __shared__ unsigned Bs[BN*SPAD];
    const int m0 = blockIdx.y*BM, n0 = blockIdx.x*BN;
    const int tid = threadIdx.x;
    const int wid = tid>>5, lane = tid&31;
    const int wm = (wid>>1)*32, wn = (wid&1)*64;
    const int r = lane>>2, q = lane&3;

    float acc[2][8][4];
    #pragma unroll
    for (int i=0;i<2;i++)
        #pragma unroll
        for (int j=0;j<8;j++)
            #pragma unroll
            for (int c=0;c<4;c++) acc[i][j][c]=0.f;

    for (int kt=0; kt<K; kt+=BK){
        __syncthreads();
        #pragma unroll
        for (int i=0;i<4;i++){
            int idx = tid + i*256;
            int row = idx>>3, c4=(idx&7)*4;
            float4 av = *(const float4*)(A + (size_t)(m0+row)*K + kt + c4);
            float4 bv = *(const float4*)(B + (size_t)(n0+row)*K + kt + c4);
            uint4 au = make_uint4(f2tf32(av.x),f2tf32(av.y),f2tf32(av.z),f2tf32(av.w));
            uint4 bu = make_uint4(f2tf32(bv.x),f2tf32(bv.y),f2tf32(bv.z),f2tf32(bv.w));
            *(uint4*)&As[row*SPAD + c4] = au;
            *(uint4*)&Bs[row*SPAD + c4] = bu;
        }
        __syncthreads();
        #pragma unroll
        for (int ks=0; ks<4; ks++){
            const int kk = ks*8;
            unsigned a[2][4], b[8][2];
            #pragma unroll
            for (int mt=0;mt<2;mt++){
                int row = wm + mt*16;
                a[mt][0]=As[(row+r  )*SPAD + kk+q  ];
                a[mt][1]=As[(row+r+8)*SPAD + kk+q  ];
                a[mt][2]=As[(row+r  )*SPAD + kk+q+4];
                a[mt][3]=As[(row+r+8)*SPAD + kk+q+4];
            }
            #pragma unroll
            for (int nt=0;nt<8;nt++){
                int col = wn + nt*8;
                b[nt][0]=Bs[(col+r)*SPAD + kk+q  ];
                b[nt][1]=Bs[(col+r)*SPAD + kk+q+4];
            }
            #pragma unroll
            for (int mt=0;mt<2;mt++){
                #pragma unroll
                for (int nt=0;nt<8;nt++){
                    asm volatile(
                        "mma.sync.aligned.m16n8k8.row.col.f32.tf32.tf32.f32 "
                        "{%0,%1,%2,%3}, {%4,%5,%6,%7}, {%8,%9}, {%0,%1,%2,%3};"
                        : "+f"(acc[mt][nt][0]),"+f"(acc[mt][nt][1]),
                          "+f"(acc[mt][nt][2]),"+f"(acc[mt][nt][3])
                        : "r"(a[mt][0]),"r"(a[mt][1]),"r"(a[mt][2]),"r"(a[mt][3]),
                          "r"(b[nt][0]),"r"(b[nt][1]));
                }
            }
        }
    }
    #pragma unroll
    for (int mt=0;mt<2;mt++){
        #pragma unroll
        for (int nt=0;nt<8;nt++){
            int row = m0 + wm + mt*16 + r;
            int col = n0 + wn + nt*8 + q*2;
            float bx=0.f, by=0.f;
            if (bias){ bx=bias[col]; by=bias[col+1]; }
            *(float2*)(C + (size_t)row*N + col) =
                make_float2(acc[mt][nt][0]+bx, acc[mt][nt][1]+by);
            *(float2*)(C + (size_t)(row+8)*N + col) =
                make_float2(acc[mt][nt][2]+bx, acc[mt][nt][3]+by);
        }
    }
}

// C[M,N] = actA(A[M,K]) @ B[K,N]; epi: 0 none, 3 sigmoid(c+bias), 4 decay(c+bias)
// actA: 0 none, 1 tanh, 2 sigmoid    (small-K LoRA stage-2, fp32)
__global__ __launch_bounds__(256) void gemm_nn64(
    const float* __restrict__ A, int lda, const float* __restrict__ B, int ldb,
    const float* __restrict__ bias, float* __restrict__ C, int ldc,
    int N, int K, int actA, int epi)
{
    __shared__ float As[16][64], Bs[16][64];
    const int m0 = blockIdx.y*64, n0 = blockIdx.x*64;
    const int tid = threadIdx.x, tx = tid & 15, ty = tid >> 4;
    const int alr = tid >> 2, alk = (tid & 3)*4;
    const int bkr = tid >> 4, bnq = (tid & 15)*4;
    float acc[4][4];
    #pragma unroll
    for (int i=0;i<4;i++){
        #pragma unroll
        for (int j=0;j<4;j++) acc[i][j]=0.f;
    }
    for (int kt=0; kt<K; kt+=16){
        float4 av = *(const float4*)(A + (size_t)(m0+alr)*lda + kt + alk);
        float4 bv = *(const float4*)(B + (size_t)(kt+bkr)*ldb + n0 + bnq);
        if (actA==1){ av.x=tanhf(av.x); av.y=tanhf(av.y); av.z=tanhf(av.z); av.w=tanhf(av.w); }
        else if (actA==2){ av.x=sigf(av.x); av.y=sigf(av.y); av.z=sigf(av.z); av.w=sigf(av.w); }
        __syncthreads();
        As[alk+0][alr]=av.x; As[alk+1][alr]=av.y; As[alk+2][alr]=av.z; As[alk+3][alr]=av.w;
        *(float4*)&Bs[bkr][bnq] = bv;
        __syncthreads();
        #pragma unroll
        for (int k=0;k<16;k++){
            float4 a4 = *(const float4*)&As[k][ty*4];
            float4 b4 = *(const float4*)&Bs[k][tx*4];
            float a[4]={a4.x,a4.y,a4.z,a4.w}, b[4]={b4.x,b4.y,b4.z,b4.w};
            #pragma unroll
            for (int i=0;i<4;i++){
                #pragma unroll
                for (int j=0;j<4;j++) acc[i][j]=fmaf(a[i],b[j],acc[i][j]);
            }
        }
    }
    const int n = n0 + tx*4;
    float bb[4]={0,0,0,0};
    if (bias){
        #pragma unroll
        for (int j=0;j<4;j++) bb[j]=bias[n+j];
    }
    #pragma unroll
    for (int ii=0; ii<4; ii++){
        int gm = m0 + ty*4 + ii;
        float o[4];
        #pragma unroll
        for (int j=0;j<4;j++){
            float c = acc[ii][j];
            if (epi==3)      c = sigf(c + bb[j]);
            else if (epi==4) c = decay_fn(c + bb[j]);
            o[j]=c;
        }
        *(float4*)(C + (size_t)gm*ldc + n) = make_float4(o[0],o[1],o[2],o[3]);
    }
}

// pack [w1|a1|v1|g1] TRANSPOSED into wcatT[512][2048]
__global__ void pack_w(const float* __restrict__ w1, const float* __restrict__ a1,
                       const float* __restrict__ v1, const float* __restrict__ g1,
                       float* __restrict__ out)
{
    int k = blockIdx.x, c = threadIdx.x;
    float val;
    if      (c < 96)  val = w1[k*96  + c];
    else if (c < 192) val = a1[k*96  + (c-96)];
    else if (c < 256) val = v1[k*64  + (c-192)];
    else              val = g1[k*256 + (c-256)];
    out[(size_t)c*Cn + k] = val;
}

// rope r/k, GQA repeat, kk normalize, k_final, v_final
__global__ __launch_bounds__(256) void prep_kernel(
    const float* __restrict__ rbuf, const float* __restrict__ kbuf, const float* __restrict__ vbuf,
    const float* __restrict__ iclr, const float* __restrict__ vsig, const float* __restrict__ vfirst,
    const float* __restrict__ cosb, const float* __restrict__ sinb,
    const float* __restrict__ k_k, const float* __restrict__ k_a,
    float* __restrict__ rrot, float* __restrict__ kkout,
    float* __restrict__ kfin, float* __restrict__ vfin)
{
    int wid = (blockIdx.x*blockDim.x + threadIdx.x) >> 5;
    int l = threadIdx.x & 31;
    int t = wid >> 5, h = wid & 31;
    int d0 = l, d1 = l+32;
    float c0 = cosb[t*64+d0], c1 = cosb[t*64+d1];
    float s0 = sinb[t*64+d0], s1 = sinb[t*64+d1];
    int base = t*Cn + h*64;
    float r0 = rbuf[base+d0], r1 = rbuf[base+d1];
    rrot[base+d0] = r0*c0 - r1*s0;
    rrot[base+d1] = r1*c1 + r0*s1;
    int kbase = t*ATTn + (h>>2)*64;
    float k0 = kbuf[kbase+d0], k1 = kbuf[kbase+d1];
    float kr0 = k0*c0 - k1*s0, kr1 = k1*c1 + k0*s1;
    float m0 = kr0 * k_k[h*64+d0], m1 = kr1 * k_k[h*64+d1];
    float ss = m0*m0 + m1*m1;
    #pragma unroll
    for (int o=16;o>0;o>>=1) ss += __shfl_xor_sync(0xffffffffu, ss, o);
    float inv = 1.0f / fmaxf(sqrtf(ss), 1e-12f);
    kkout[base+d0] = m0*inv; kkout[base+d1] = m1*inv;
    float ic0 = iclr[base+d0], ic1 = iclr[base+d1];
    kfin[base+d0] = kr0 * (1.0f + (ic0-1.0f)*k_a[h*64+d0]);
    kfin[base+d1] = kr1 * (1.0f + (ic1-1.0f)*k_a[h*64+d1]);
    float v0v = vbuf[kbase+d0], v1v = vbuf[kbase+d1];
    vfin[base+d0] = v0v + (vfirst[base+d0]-v0v)*vsig[base+d0];
    vfin[base+d1] = v1v + (vfirst[base+d1]-v1v)*vsig[base+d1];
}

// sequential scan: 128 CTAs = 4 per head; 16 rows x 8 lanes; S in registers
__global__ __launch_bounds__(128) void scan_kernel(
    const float* __restrict__ wdec, const float* __restrict__ kkb,
    const float* __restrict__ aic,  const float* __restrict__ kf,
    const float* __restrict__ vf,   const float* __restrict__ rr,
    const float* __restrict__ s_in, float* __restrict__ yout, float* __restrict__ s_out)
{
    const int b = blockIdx.x, h = b >> 2, rbk = b & 3;
    const int tid = threadIdx.x, rl = tid >> 3, sub = tid & 7;
    const int i = rbk*16 + rl, cb = sub*8;
    const int coff = h*64 + cb, voff = h*64 + i;

    float S[8];
    { const float4* sp = (const float4*)(s_in + (size_t)(h*64 + i)*64 + cb);
      float4 a = sp[0], c = sp[1];
      S[0]=a.x;S[1]=a.y;S[2]=a.z;S[3]=a.w;S[4]=c.x;S[5]=c.y;S[6]=c.z;S[7]=c.w; }

    float4 Bw[2][2], Bk[2][2], Ba[2][2], Bf[2][2], Br[2][2];
    float Bv[2];
    #pragma unroll
    for (int p=0;p<2;p++){
        size_t t0 = (size_t)p*Cn;
        Bw[p][0]=((const float4*)(wdec+t0+coff))[0]; Bw[p][1]=((const float4*)(wdec+t0+coff))[1];
        Bk[p][0]=((const float4*)(kkb +t0+coff))[0]; Bk[p][1]=((const float4*)(kkb +t0+coff))[1];
        Ba[p][0]=((const float4*)(aic +t0+coff))[0]; Ba[p][1]=((const float4*)(aic +t0+coff))[1];
        Bf[p][0]=((const float4*)(kf  +t0+coff))[0]; Bf[p][1]=((const float4*)(kf  +t0+coff))[1];
        Br[p][0]=((const float4*)(rr  +t0+coff))[0]; Br[p][1]=((const float4*)(rr  +t0+coff))[1];
        Bv[p] = vf[t0 + voff];
    }

    #pragma unroll 2
    for (int t=0; t<Tn; t++){
        const int p = t & 1;
        float w[8], kv[8], av[8], fv[8], rv[8];
        { float4 x0=Bw[p][0], x1=Bw[p][1]; w[0]=x0.x;w[1]=x0.y;w[2]=x0.z;w[3]=x0.w;w[4]=x1.x;w[5]=x1.y;w[6]=x1.z;w[7]=x1.w; }
        { float4 x0=Bk[p][0], x1=Bk[p][1]; kv[0]=x0.x;kv[1]=x0.y;kv[2]=x0.z;kv[3]=x0.w;kv[4]=x1.x;kv[5]=x1.y;kv[6]=x1.z;kv[7]=x1.w; }
        { float4 x0=Ba[p][0], x1=Ba[p][1]; av[0]=x0.x;av[1]=x0.y;av[2]=x0.z;av[3]=x0.w;av[4]=x1.x;av[5]=x1.y;av[6]=x1.z;av[7]=x1.w; }
        { float4 x0=Bf[p][0], x1=Bf[p][1]; fv[0]=x0.x;fv[1]=x0.y;fv[2]=x0.z;fv[3]=x0.w;fv[4]=x1.x;fv[5]=x1.y;fv[6]=x1.z;fv[7]=x1.w; }
        { float4 x0=Br[p][0], x1=Br[p][1]; rv[0]=x0.x;rv[1]=x0.y;rv[2]=x0.z;rv[3]=x0.w;rv[4]=x1.x;rv[5]=x1.y;rv[6]=x1.z;rv[7]=x1.w; }
        float vi = Bv[p];
        { // prefetch t+2
            const size_t t2 = (size_t)(t + 2)*Cn;
            Bw[p][0]=((const float4*)(wdec+t2+coff))[0]; Bw[p][1]=((const float4*)(wdec+t2+coff))[1];
            Bk[p][0]=((const float4*)(kkb +t2+coff))[0]; Bk[p][1]=((const float4*)(kkb +t2+coff))[1];
            Ba[p][0]=((const float4*)(aic +t2+coff))[0]; Ba[p][1]=((const float4*)(aic +t2+coff))[1];
            Bf[p][0]=((const float4*)(kf  +t2+coff))[0]; Bf[p][1]=((const float4*)(kf  +t2+coff))[1];
            Br[p][0]=((const float4*)(rr  +t2+coff))[0]; Br[p][1]=((const float4*)(rr  +t2+coff))[1];
            Bv[p] = vf[t2 + voff];
        }
        float sd0=0.f, sd1=0.f;
        #pragma unroll
        for (int q=0;q<4;q++){ sd0 = fmaf(S[q],kv[q],sd0); sd1 = fmaf(S[q+4],kv[q+4],sd1); }
        float sd = sd0 + sd1;
        sd += __shfl_xor_sync(0xffffffffu, sd, 1);
        sd += __shfl_xor_sync(0xffffffffu, sd, 2);
        sd += __shfl_xor_sync(0xffffffffu, sd, 4);
        float y0=0.f, y1=0.f;
        #pragma unroll
        for (int q=0;q<8;q++){
            float ab  = kv[q]*av[q];
            float tmp = fmaf(S[q], w[q], vi*fv[q]);
            S[q] = fmaf(-sd, ab, tmp);
            if (q<4) y0 = fmaf(S[q], rv[q], y0); else y1 = fmaf(S[q], rv[q], y1);
        }
        float yv = y0+y1;
        yv += __shfl_xor_sync(0xffffffffu, yv, 1);
        yv += __shfl_xor_sync(0xffffffffu, yv, 2);
        yv += __shfl_xor_sync(0xffffffffu, yv, 4);
        if (sub==0) yout[(size_t)t*Cn + voff] = yv;
    }
    float4* so = (float4*)(s_out + (size_t)(h*64+i)*64 + cb);
    so[0] = make_float4(S[0],S[1],S[2],S[3]);
    so[1] = make_float4(S[4],S[5],S[6],S[7]);
}

// groupnorm + ln + bonus + gate
__global__ __launch_bounds__(256) void post_kernel(
    const float* __restrict__ y, const float* __restrict__ rrot,
    const float* __restrict__ kfin, const float* __restrict__ vfin,
    const float* __restrict__ gate, const float* __restrict__ r_k,
    const float* __restrict__ ln_w, const float* __restrict__ ln_b,
    float* __restrict__ z)
{
    int wid = (blockIdx.x*blockDim.x + threadIdx.x) >> 5;
    int l = threadIdx.x & 31;
    int t = wid >> 5, h = wid & 31;
    int base = t*Cn + h*64;
    int d0 = l, d1 = l+32;
    float y0 = y[base+d0], y1 = y[base+d1];
    float s = y0+y1, sq = y0*y0 + y1*y1;
    float r0 = rrot[base+d0], r1 = rrot[base+d1];
    float dot = r0*kfin[base+d0]*r_k[h*64+d0] + r1*kfin[base+d1]*r_k[h*64+d1];
    #pragma unroll
    for (int o=16;o>0;o>>=1){
        s   += __shfl_xor_sync(0xffffffffu, s, o);
        sq  += __shfl_xor_sync(0xffffffffu, sq, o);
        dot += __shfl_xor_sync(0xffffffffu, dot, o);
    }
    float mu = s * (1.0f/64.0f);
    float var = sq * (1.0f/64.0f) - mu*mu;
    float rstd = rsqrtf(var + 6.4e-4f);
    float n0 = (y0-mu)*rstd*ln_w[h*64+d0] + ln_b[h*64+d0];
    float n1 = (y1-mu)*rstd*ln_w[h*64+d1] + ln_b[h*64+d1];
    z[base+d0] = (n0 + dot*vfin[base+d0]) * gate[base+d0];
    z[base+d1] = (n1 + dot*vfin[base+d1]) * gate[base+d1];
}

extern "C" void kernel_launch(void* const* d_in, const int* in_sizes, int n_in,
                              void* d_out, int out_size) {
    const float* x       = (const float*)d_in[0];
    const float* wkv_in  = (const float*)d_in[1];
    const float* v_first = (const float*)d_in[2];
    const float* cosb    = (const float*)d_in[3];
    const float* sinb    = (const float*)d_in[4];
    const float* w0      = (const float*)d_in[5];
    const float* w1      = (const float*)d_in[6];
    const float* w2      = (const float*)d_in[7];
    const float* a0      = (const float*)d_in[8];
    const float* a1      = (const float*)d_in[9];
    const float* a2      = (const float*)d_in[10];
    const float* v0      = (const float*)d_in[11];
    const float* v1      = (const float*)d_in[12];
    const float* v2      = (const float*)d_in[13];
    const float* g1      = (const float*)d_in[14];
    const float* g2      = (const float*)d_in[15];
    const float* k_k     = (const float*)d_in[16];
    const float* k_a     = (const float*)d_in[17];
    const float* r_k     = (const float*)d_in[18];
    const float* q_w     = (const float*)d_in[19];
    const float* q_b     = (const float*)d_in[20];
    const float* k_w     = (const float*)d_in[21];
    const float* k_b     = (const float*)d_in[22];
    const float* v_w     = (const float*)d_in[23];
    const float* v_b     = (const float*)d_in[24];
    const float* o_w     = (const float*)d_in[25];
    const float* ln_w    = (const float*)d_in[26];
    const float* ln_b    = (const float*)d_in[27];

    float* out   = (float*)d_out;
    float* s_out = out + (size_t)Tn*Cn;
    float* vf_out = s_out + 32*64*64;

    float *p_r, *p_k, *p_v, *p_wcatT, *p_h1, *p_wdec, *p_iclr, *p_vsig, *p_gate;
    float *p_rrot, *p_kfin, *p_vfin, *p_kk, *p_y, *p_z;
    cudaGetSymbolAddress((void**)&p_r, g_r);
    cudaGetSymbolAddress((void**)&p_k, g_k);
    cudaGetSymbolAddress((void**)&p_v, g_v);
    cudaGetSymbolAddress((void**)&p_wcatT, g_wcatT);
    cudaGetSymbolAddress((void**)&p_h1, g_h1);
    cudaGetSymbolAddress((void**)&p_wdec, g_wdec);
    cudaGetSymbolAddress((void**)&p_iclr, g_iclr);
    cudaGetSymbolAddress((void**)&p_vsig, g_vsig);
    cudaGetSymbolAddress((void**)&p_gate, g_gate);
    cudaGetSymbolAddress((void**)&p_rrot, g_rrot);
    cudaGetSymbolAddress((void**)&p_kfin, g_kfin);
    cudaGetSymbolAddress((void**)&p_vfin, g_vfin);
    cudaGetSymbolAddress((void**)&p_kk, g_kk);
    cudaGetSymbolAddress((void**)&p_y, g_y);
    cudaGetSymbolAddress((void**)&p_z, g_z);

    pack_w<<<Cn,512>>>(w1, a1, v1, g1, p_wcatT);
    gemm_nt_tf32<<<dim3(16,16),256>>>(x, q_w, q_b, p_r, Cn, Cn);
    gemm_nt_tf32<<<dim3(4,16),256>>>(x, k_w, k_b, p_k, ATTn, Cn);
    gemm_nt_tf32<<<dim3(4,16),256>>>(x, v_w, v_b, p_v, ATTn, Cn);
    gemm_nt_tf32<<<dim3(4,16),256>>>(x, p_wcatT, nullptr, p_h1, 512, Cn);
    gemm_nn64 <<<dim3(32,32),256>>>(p_h1+0,   512, w2, Cn, w0,      p_wdec, Cn, Cn,  96, 1, 4);
    gemm_nn64 <<<dim3(32,32),256>>>(p_h1+96,  512, a2, Cn, a0,      p_iclr, Cn, Cn,  96, 0, 3);
    gemm_nn64 <<<dim3(32,32),256>>>(p_h1+192, 512, v2, Cn, v0,      p_vsig, Cn, Cn,  64, 0, 3);
    gemm_nn64 <<<dim3(32,32),256>>>(p_h1+256, 512, g2, Cn, nullptr, p_gate, Cn, Cn, 256, 2, 0);
    prep_kernel<<<8192,256>>>(p_r, p_k, p_v, p_iclr, p_vsig, v_first, cosb, sinb,
                              k_k, k_a, p_rrot, p_kk, p_kfin, p_vfin);
    scan_kernel<<<128,128>>>(p_wdec, p_kk, p_iclr, p_kfin, p_vfin, p_rrot,
                             wkv_in, p_y, s_out);
    post_kernel<<<8192,256>>>(p_y, p_rrot, p_kfin, p_vfin, p_gate, r_k, ln_w, ln_b, p_z);
    gemm_nt_tf32<<<dim3(16,16),256>>>(p_z, o_w, nullptr, out, Cn, Cn);
    cudaMemcpyAsync(vf_out, v_first, (size_t)Tn*Cn*sizeof(float),
                    cudaMemcpyDeviceToDevice, 0);
}

// round 5
// speedup vs baseline: 1.5994x; 1.1573x over previous
#include <cuda_runtime.h>
#include <cuda_bf16.h>
#include <math.h>

#define Tn   2048
#define Cn   2048
#define Nfused 3584

// scratch (device globals are zero-initialized; +2 row padding for scan prefetch)
__device__ float g_bigB[Nfused*Cn];
__device__ float g_bigBias[Nfused];
__device__ float g_qkvh[Tn*Nfused];
__device__ float g_wdec[(Tn+2)*Cn];
__device__ float g_iclr[(Tn+2)*Cn];
__device__ float g_vsig[Tn*Cn];
__device__ float g_gate[Tn*Cn];
__device__ float g_rrot[(Tn+2)*Cn];
__device__ float g_kfin[(Tn+2)*Cn];
__device__ float g_vfin[(Tn+2)*Cn];
__device__ float g_kk  [(Tn+2)*Cn];
__device__ float g_y[Tn*Cn];
__device__ float g_z[Tn*Cn];

__device__ __forceinline__ float sigf(float x){ return 1.0f/(1.0f + expf(-x)); }
__device__ __forceinline__ float decay_fn(float v){
    float nv = -v;
    float sp = (nv > 20.0f) ? nv : log1pf(expf(nv));
    return expf(-expf(-sp - 0.5f));
}
__device__ __forceinline__ unsigned f2tf32(float f){
    unsigned u;
    asm("cvt.rna.tf32.f32 %0, %1;" : "=r"(u) : "f"(f));
    return u;
}

#define CP16(sm, gp) asm volatile("cp.async.cg.shared.global [%0], [%1], 16;\n" :: "r"(sm), "l"(gp))
#define CPCOMMIT()   asm volatile("cp.async.commit_group;\n" ::)
#define CPWAIT2()    asm volatile("cp.async.wait_group 2;\n" ::)

// swizzled smem index: 16-word rows, conflict-free fragment access
__device__ __forceinline__ int SW(int row, int col){
    return row*16 + (col ^ (4*((row>>1)&3)));
}

// ---------------- pipelined TF32 tensor-core GEMM: C[M,N] = A[M,K] @ B[N,K]^T + bias ----------------
// 128x128x16 tile, 3-stage cp.async pipeline, 256 threads = 8 warps (4x2), warp tile 32x64
__global__ __launch_bounds__(256) void gemm_nt_tf32(
    const float* __restrict__ A, const float* __restrict__ B,
    const float* __restrict__ bias, float* __restrict__ C, int N, int K)
{
    __shared__ float As[3][128*16];
    __shared__ float Bs[3][128*16];
    const int m0 = blockIdx.y*128, n0 = blockIdx.x*128;
    const int tid = threadIdx.x;
    const int wid = tid>>5, lane = tid&31;
    const int wm = (wid>>1)*32, wn = (wid&1)*64;
    const int r = lane>>2, q = lane&3;

    const int row0 = tid>>2, c40 = (tid&3)*4;   // 2 chunks per matrix per thread
    const int row1 = row0 + 64;
    const float* Ag = A + (size_t)m0*K;
    const float* Bg = B + (size_t)n0*K;
    const size_t a0off = (size_t)row0*K + c40;
    const size_t a1off = (size_t)row1*K + c40;

    float acc[2][8][4];
    #pragma unroll
    for (int i=0;i<2;i++)
        #pragma unroll
        for (int j=0;j<8;j++)
            #pragma unroll
            for (int c=0;c<4;c++) acc[i][j][c]=0.f;

    const int niter = K/16;
    // prologue: tiles 0,1
    #pragma unroll
    for (int p=0;p<2;p++){
        unsigned sa = (unsigned)__cvta_generic_to_shared(&As[p][0]);
        unsigned sb = (unsigned)__cvta_generic_to_shared(&Bs[p][0]);
        const float* ag = Ag + p*16;
        const float* bg = Bg + p*16;
        CP16(sa + SW(row0,c40)*4, ag + a0off);
        CP16(sa + SW(row1,c40)*4, ag + a1off);
        CP16(sb + SW(row0,c40)*4, bg + a0off);
        CP16(sb + SW(row1,c40)*4, bg + a1off);
        CPCOMMIT();
    }

    for (int it=0; it<niter; it++){
        const int nx = it+2;
        if (nx < niter){
            const int buf = nx%3;
            unsigned sa = (unsigned)__cvta_generic_to_shared(&As[buf][0]);
            unsigned sb = (unsigned)__cvta_generic_to_shared(&Bs[buf][0]);
            const float* ag = Ag + nx*16;
            const float* bg = Bg + nx*16;
            CP16(sa + SW(row0,c40)*4, ag + a0off);
            CP16(sa + SW(row1,c40)*4, ag + a1off);
            CP16(sb + SW(row0,c40)*4, bg + a0off);
            CP16(sb + SW(row1,c40)*4, bg + a1off);
        }
        CPCOMMIT();
        CPWAIT2();
        __syncthreads();
        const float* as = As[it%3];
        const float* bs = Bs[it%3];
        #pragma unroll
        for (int ks=0; ks<2; ks++){
            const int kk = ks*8;
            unsigned a[2][4], b[8][2];
            #pragma unroll
            for (int mt=0;mt<2;mt++){
                const int row = wm + mt*16;
                a[mt][0]=f2tf32(as[SW(row+r,  kk+q  )]);
                a[mt][1]=f2tf32(as[SW(row+r+8,kk+q  )]);
                a[mt][2]=f2tf32(as[SW(row+r,  kk+q+4)]);
                a[mt][3]=f2tf32(as[SW(row+r+8,kk+q+4)]);
            }
            #pragma unroll
            for (int nt=0;nt<8;nt++){
                const int col = wn + nt*8;
                b[nt][0]=f2tf32(bs[SW(col+r, kk+q  )]);
                b[nt][1]=f2tf32(bs[SW(col+r, kk+q+4)]);
            }
            #pragma unroll
            for (int mt=0;mt<2;mt++){
                #pragma unroll
                for (int nt=0;nt<8;nt++){
                    asm volatile(
                        "mma.sync.aligned.m16n8k8.row.col.f32.tf32.tf32.f32 "
                        "{%0,%1,%2,%3}, {%4,%5,%6,%7}, {%8,%9}, {%0,%1,%2,%3};"
                        : "+f"(acc[mt][nt][0]),"+f"(acc[mt][nt][1]),
                          "+f"(acc[mt][nt][2]),"+f"(acc[mt][nt][3])
                        : "r"(a[mt][0]),"r"(a[mt][1]),"r"(a[mt][2]),"r"(a[mt][3]),
                          "r"(b[nt][0]),"r"(b[nt][1]));
                }
            }
        }
        __syncthreads();
    }
    #pragma unroll
    for (int mt=0;mt<2;mt++){
        #pragma unroll
        for (int nt=0;nt<8;nt++){
            int row = m0 + wm + mt*16 + r;
            int col = n0 + wn + nt*8 + q*2;
            float bx=0.f, by=0.f;
            if (bias){ bx=bias[col]; by=bias[col+1]; }
            *(float2*)(C + (size_t)row*N + col) =
                make_float2(acc[mt][nt][0]+bx, acc[mt][nt][1]+by);
            *(float2*)(C + (size_t)(row+8)*N + col) =
                make_float2(acc[mt][nt][2]+bx, acc[mt][nt][3]+by);
        }
    }
}

// C[M,N] = actA(A[M,K]) @ B[K,N]; epi: 0 none, 3 sigmoid(c+bias), 4 decay(c+bias)
// actA: 0 none, 1 tanh, 2 sigmoid    (small-K LoRA stage-2, fp32)
__global__ __launch_bounds__(256) void gemm_nn64(
    const float* __restrict__ A, int lda, const float* __restrict__ B, int ldb,
    const float* __restrict__ bias, float* __restrict__ C, int ldc,
    int N, int K, int actA, int epi)
{
    __shared__ float As[16][64], Bs[16][64];
    const int m0 = blockIdx.y*64, n0 = blockIdx.x*64;
    const int tid = threadIdx.x, tx = tid & 15, ty = tid >> 4;
    const int alr = tid >> 2, alk = (tid & 3)*4;
    const int bkr = tid >> 4, bnq = (tid & 15)*4;
    float acc[4][4];
    #pragma unroll
    for (int i=0;i<4;i++){
        #pragma unroll
        for (int j=0;j<4;j++) acc[i][j]=0.f;
    }
    for (int kt=0; kt<K; kt+=16){
        float4 av = *(const float4*)(A + (size_t)(m0+alr)*lda + kt + alk);
        float4 bv = *(const float4*)(B + (size_t)(kt+bkr)*ldb + n0 + bnq);
        if (actA==1){ av.x=tanhf(av.x); av.y=tanhf(av.y); av.z=tanhf(av.z); av.w=tanhf(av.w); }
        else if (actA==2){ av.x=sigf(av.x); av.y=sigf(av.y); av.z=sigf(av.z); av.w=sigf(av.w); }
        __syncthreads();
        As[alk+0][alr]=av.x; As[alk+1][alr]=av.y; As[alk+2][alr]=av.z; As[alk+3][alr]=av.w;
        *(float4*)&Bs[bkr][bnq] = bv;
        __syncthreads();
        #pragma unroll
        for (int k=0;k<16;k++){
            float4 a4 = *(const float4*)&As[k][ty*4];
            float4 b4 = *(const float4*)&Bs[k][tx*4];
            float a[4]={a4.x,a4.y,a4.z,a4.w}, b[4]={b4.x,b4.y,b4.z,b4.w};
            #pragma unroll
            for (int i=0;i<4;i++){
                #pragma unroll
                for (int j=0;j<4;j++) acc[i][j]=fmaf(a[i],b[j],acc[i][j]);
            }
        }
    }
    const int n = n0 + tx*4;
    float bb[4]={0,0,0,0};
    if (bias){
        #pragma unroll
        for (int j=0;j<4;j++) bb[j]=bias[n+j];
    }
    #pragma unroll
    for (int ii=0; ii<4; ii++){
        int gm = m0 + ty*4 + ii;
        float o[4];
        #pragma unroll
        for (int j=0;j<4;j++){
            float c = acc[ii][j];
            if (epi==3)      c = sigf(c + bb[j]);
            else if (epi==4) c = decay_fn(c + bb[j]);
            o[j]=c;
        }
        *(float4*)(C + (size_t)gm*ldc + n) = make_float4(o[0],o[1],o[2],o[3]);
    }
}

// pack fused B = [q_w ; k_w ; v_w ; wcatT] rows, and fused bias
__global__ void pack_B(const float* __restrict__ q_w, const float* __restrict__ k_w,
                       const float* __restrict__ v_w,
                       const float* __restrict__ w1, const float* __restrict__ a1,
                       const float* __restrict__ v1, const float* __restrict__ g1,
                       const float* __restrict__ q_b, const float* __restrict__ k_b,
                       const float* __restrict__ v_b,
                       float* __restrict__ Bout, float* __restrict__ biasOut)
{
    int row = blockIdx.x;
    for (int col = threadIdx.x; col < Cn; col += blockDim.x){
        float v;
        if (row < 2048)       v = q_w[(size_t)row*Cn + col];
        else if (row < 2560)  v = k_w[(size_t)(row-2048)*Cn + col];
        else if (row < 3072)  v = v_w[(size_t)(row-2560)*Cn + col];
        else {
            int c = row - 3072;
            if      (c < 96)  v = w1[(size_t)col*96  + c];
            else if (c < 192) v = a1[(size_t)col*96  + (c-96)];
            else if (c < 256) v = v1[(size_t)col*64  + (c-192)];
            else              v = g1[(size_t)col*256 + (c-256)];
        }
        Bout[(size_t)row*Cn + col] = v;
    }
    if (threadIdx.x == 0){
        float bv = 0.f;
        if (row < 2048)      bv = q_b[row];
        else if (row < 2560) bv = k_b[row-2048];
        else if (row < 3072) bv = v_b[row-2560];
        biasOut[row] = bv;
    }
}

// rope r/k, GQA repeat, kk normalize, k_final, v_final  (reads fused qkvh buffer)
__global__ __launch_bounds__(256) void prep_kernel(
    const float* __restrict__ qkvh,
    const float* __restrict__ iclr, const float* __restrict__ vsig, const float* __restrict__ vfirst,
    const float* __restrict__ cosb, const float* __restrict__ sinb,
    const float* __restrict__ k_k, const float* __restrict__ k_a,
    float* __restrict__ rrot, float* __restrict__ kkout,
    float* __restrict__ kfin, float* __restrict__ vfin)
{
    int wid = (blockIdx.x*blockDim.x + threadIdx.x) >> 5;
    int l = threadIdx.x & 31;
    int t = wid >> 5, h = wid & 31;
    int d0 = l, d1 = l+32;
    float c0 = cosb[t*64+d0], c1 = cosb[t*64+d1];
    float s0 = sinb[t*64+d0], s1 = sinb[t*64+d1];
    int base = t*Cn + h*64;                         // output base (stride Cn)
    int rbase = t*Nfused + h*64;                    // q in fused
    int kbase = t*Nfused + 2048 + (h>>2)*64;        // k in fused
    int vbase = t*Nfused + 2560 + (h>>2)*64;        // v in fused
    float r0 = qkvh[rbase+d0], r1 = qkvh[rbase+d1];
    rrot[base+d0] = r0*c0 - r1*s0;
    rrot[base+d1] = r1*c1 + r0*s1;
    float k0 = qkvh[kbase+d0], k1 = qkvh[kbase+d1];
    float kr0 = k0*c0 - k1*s0, kr1 = k1*c1 + k0*s1;
    float m0 = kr0 * k_k[h*64+d0], m1 = kr1 * k_k[h*64+d1];
    float ss = m0*m0 + m1*m1;
    #pragma unroll
    for (int o=16;o>0;o>>=1) ss += __shfl_xor_sync(0xffffffffu, ss, o);
    float inv = 1.0f / fmaxf(sqrtf(ss), 1e-12f);
    kkout[base+d0] = m0*inv; kkout[base+d1] = m1*inv;
    float ic0 = iclr[base+d0], ic1 = iclr[base+d1];
    kfin[base+d0] = kr0 * (1.0f + (ic0-1.0f)*k_a[h*64+d0]);
    kfin[base+d1] = kr1 * (1.0f + (ic1-1.0f)*k_a[h*64+d1]);
    float v0v = qkvh[vbase+d0], v1v = qkvh[vbase+d1];
    vfin[base+d0] = v0v + (vfirst[base+d0]-v0v)*vsig[base+d0];
    vfin[base+d1] = v1v + (vfirst[base+d1]-v1v)*vsig[base+d1];
}

// sequential scan: 128 CTAs = 4 per head; 16 rows x 8 lanes; S in registers
__global__ __launch_bounds__(128) void scan_kernel(
    const float* __restrict__ wdec, const float* __restrict__ kkb,
    const float* __restrict__ aic,  const float* __restrict__ kf,
    const float* __restrict__ vf,   const float* __restrict__ rr,
    const float* __restrict__ s_in, float* __restrict__ yout, float* __restrict__ s_out)
{
    const int b = blockIdx.x, h = b >> 2, rbk = b & 3;
    const int tid = threadIdx.x, rl = tid >> 3, sub = tid & 7;
    const int i = rbk*16 + rl, cb = sub*8;
    const int coff = h*64 + cb, voff = h*64 + i;

    float S[8];
    { const float4* sp = (const float4*)(s_in + (size_t)(h*64 + i)*64 + cb);
      float4 a = sp[0], c = sp[1];
      S[0]=a.x;S[1]=a.y;S[2]=a.z;S[3]=a.w;S[4]=c.x;S[5]=c.y;S[6]=c.z;S[7]=c.w; }

    float4 Bw[2][2], Bk[2][2], Ba[2][2], Bf[2][2], Br[2][2];
    float Bv[2];
    #pragma unroll
    for (int p=0;p<2;p++){
        size_t t0 = (size_t)p*Cn;
        Bw[p][0]=((const float4*)(wdec+t0+coff))[0]; Bw[p][1]=((const float4*)(wdec+t0+coff))[1];
        Bk[p][0]=((const float4*)(kkb +t0+coff))[0]; Bk[p][1]=((const float4*)(kkb +t0+coff))[1];
        Ba[p][0]=((const float4*)(aic +t0+coff))[0]; Ba[p][1]=((const float4*)(aic +t0+coff))[1];
        Bf[p][0]=((const float4*)(kf  +t0+coff))[0]; Bf[p][1]=((const float4*)(kf  +t0+coff))[1];
        Br[p][0]=((const float4*)(rr  +t0+coff))[0]; Br[p][1]=((const float4*)(rr  +t0+coff))[1];
        Bv[p] = vf[t0 + voff];
    }

    #pragma unroll 2
    for (int t=0; t<Tn; t++){
        const int p = t & 1;
        float w[8], kv[8], av[8], fv[8], rv[8];
        { float4 x0=Bw[p][0], x1=Bw[p][1]; w[0]=x0.x;w[1]=x0.y;w[2]=x0.z;w[3]=x0.w;w[4]=x1.x;w[5]=x1.y;w[6]=x1.z;w[7]=x1.w; }
        { float4 x0=Bk[p][0], x1=Bk[p][1]; kv[0]=x0.x;kv[1]=x0.y;kv[2]=x0.z;kv[3]=x0.w;kv[4]=x1.x;kv[5]=x1.y;kv[6]=x1.z;kv[7]=x1.w; }
        { float4 x0=Ba[p][0], x1=Ba[p][1]; av[0]=x0.x;av[1]=x0.y;av[2]=x0.z;av[3]=x0.w;av[4]=x1.x;av[5]=x1.y;av[6]=x1.z;av[7]=x1.w; }
        { float4 x0=Bf[p][0], x1=Bf[p][1]; fv[0]=x0.x;fv[1]=x0.y;fv[2]=x0.z;fv[3]=x0.w;fv[4]=x1.x;fv[5]=x1.y;fv[6]=x1.z;fv[7]=x1.w; }
        { float4 x0=Br[p][0], x1=Br[p][1]; rv[0]=x0.x;rv[1]=x0.y;rv[2]=x0.z;rv[3]=x0.w;rv[4]=x1.x;rv[5]=x1.y;rv[6]=x1.z;rv[7]=x1.w; }
        float vi = Bv[p];
        { // prefetch t+2
            const size_t t2 = (size_t)(t + 2)*Cn;
            Bw[p][0]=((const float4*)(wdec+t2+coff))[0]; Bw[p][1]=((const float4*)(wdec+t2+coff))[1];
            Bk[p][0]=((const float4*)(kkb +t2+coff))[0]; Bk[p][1]=((const float4*)(kkb +t2+coff))[1];
            Ba[p][0]=((const float4*)(aic +t2+coff))[0]; Ba[p][1]=((const float4*)(aic +t2+coff))[1];
            Bf[p][0]=((const float4*)(kf  +t2+coff))[0]; Bf[p][1]=((const float4*)(kf  +t2+coff))[1];
            Br[p][0]=((const float4*)(rr  +t2+coff))[0]; Br[p][1]=((const float4*)(rr  +t2+coff))[1];
            Bv[p] = vf[t2 + voff];
        }
        float sd0=0.f, sd1=0.f;
        #pragma unroll
        for (int q=0;q<4;q++){ sd0 = fmaf(S[q],kv[q],sd0); sd1 = fmaf(S[q+4],kv[q+4],sd1); }
        float sd = sd0 + sd1;
        sd += __shfl_xor_sync(0xffffffffu, sd, 1);
        sd += __shfl_xor_sync(0xffffffffu, sd, 2);
        sd += __shfl_xor_sync(0xffffffffu, sd, 4);
        float y0=0.f, y1=0.f;
        #pragma unroll
        for (int q=0;q<8;q++){
            float ab  = kv[q]*av[q];
            float tmp = fmaf(S[q], w[q], vi*fv[q]);
            S[q] = fmaf(-sd, ab, tmp);
            if (q<4) y0 = fmaf(S[q], rv[q], y0); else y1 = fmaf(S[q], rv[q], y1);
        }
        float yv = y0+y1;
        yv += __shfl_xor_sync(0xffffffffu, yv, 1);
        yv += __shfl_xor_sync(0xffffffffu, yv, 2);
        yv += __shfl_xor_sync(0xffffffffu, yv, 4);
        if (sub==0) yout[(size_t)t*Cn + voff] = yv;
    }
    float4* so = (float4*)(s_out + (size_t)(h*64+i)*64 + cb);
    so[0] = make_float4(S[0],S[1],S[2],S[3]);
    so[1] = make_float4(S[4],S[5],S[6],S[7]);
}

// groupnorm + ln + bonus + gate
__global__ __launch_bounds__(256) void post_kernel(
    const float* __restrict__ y, const float* __restrict__ rrot,
    const float* __restrict__ kfin, const float* __restrict__ vfin,
    const float* __restrict__ gate, const float* __restrict__ r_k,
    const float* __restrict__ ln_w, const float* __restrict__ ln_b,
    float* __restrict__ z)
{
    int wid = (blockIdx.x*blockDim.x + threadIdx.x) >> 5;
    int l = threadIdx.x & 31;
    int t = wid >> 5, h = wid & 31;
    int base = t*Cn + h*64;
    int d0 = l, d1 = l+32;
    float y0 = y[base+d0], y1 = y[base+d1];
    float s = y0+y1, sq = y0*y0 + y1*y1;
    float r0 = rrot[base+d0], r1 = rrot[base+d1];
    float dot = r0*kfin[base+d0]*r_k[h*64+d0] + r1*kfin[base+d1]*r_k[h*64+d1];
    #pragma unroll
    for (int o=16;o>0;o>>=1){
        s   += __shfl_xor_sync(0xffffffffu, s, o);
        sq  += __shfl_xor_sync(0xffffffffu, sq, o);
        dot += __shfl_xor_sync(0xffffffffu, dot, o);
    }
    float mu = s * (1.0f/64.0f);
    float var = sq * (1.0f/64.0f) - mu*mu;
    float rstd = rsqrtf(var + 6.4e-4f);
    float n0 = (y0-mu)*rstd*ln_w[h*64+d0] + ln_b[h*64+d0];
    float n1 = (y1-mu)*rstd*ln_w[h*64+d1] + ln_b[h*64+d1];
    z[base+d0] = (n0 + dot*vfin[base+d0]) * gate[base+d0];
    z[base+d1] = (n1 + dot*vfin[base+d1]) * gate[base+d1];
}

extern "C" void kernel_launch(void* const* d_in, const int* in_sizes, int n_in,
                              void* d_out, int out_size) {
    const float* x       = (const float*)d_in[0];
    const float* wkv_in  = (const float*)d_in[1];
    const float* v_first = (const float*)d_in[2];
    const float* cosb    = (const float*)d_in[3];
    const float* sinb    = (const float*)d_in[4];
    const float* w0      = (const float*)d_in[5];
    const float* w1      = (const float*)d_in[6];
    const float* w2      = (const float*)d_in[7];
    const float* a0      = (const float*)d_in[8];
    const float* a1      = (const float*)d_in[9];
    const float* a2      = (const float*)d_in[10];
    const float* v0      = (const float*)d_in[11];
    const float* v1      = (const float*)d_in[12];
    const float* v2      = (const float*)d_in[13];
    const float* g1      = (const float*)d_in[14];
    const float* g2      = (const float*)d_in[15];
    const float* k_k     = (const float*)d_in[16];
    const float* k_a     = (const float*)d_in[17];
    const float* r_k     = (const float*)d_in[18];
    const float* q_w     = (const float*)d_in[19];
    const float* q_b     = (const float*)d_in[20];
    const float* k_w     = (const float*)d_in[21];
    const float* k_b     = (const float*)d_in[22];
    const float* v_w     = (const float*)d_in[23];
    const float* v_b     = (const float*)d_in[24];
    const float* o_w     = (const float*)d_in[25];
    const float* ln_w    = (const float*)d_in[26];
    const float* ln_b    = (const float*)d_in[27];

    float* out   = (float*)d_out;
    float* s_out = out + (size_t)Tn*Cn;
    float* vf_out = s_out + 32*64*64;

    float *p_bigB, *p_bigBias, *p_qkvh, *p_wdec, *p_iclr, *p_vsig, *p_gate;
    float *p_rrot, *p_kfin, *p_vfin, *p_kk, *p_y, *p_z;
    cudaGetSymbolAddress((void**)&p_bigB, g_bigB);
    cudaGetSymbolAddress((void**)&p_bigBias, g_bigBias);
    cudaGetSymbolAddress((void**)&p_qkvh, g_qkvh);
    cudaGetSymbolAddress((void**)&p_wdec, g_wdec);
    cudaGetSymbolAddress((void**)&p_iclr, g_iclr);
    cudaGetSymbolAddress((void**)&p_vsig, g_vsig);
    cudaGetSymbolAddress((void**)&p_gate, g_gate);
    cudaGetSymbolAddress((void**)&p_rrot, g_rrot);
    cudaGetSymbolAddress((void**)&p_kfin, g_kfin);
    cudaGetSymbolAddress((void**)&p_vfin, g_vfin);
    cudaGetSymbolAddress((void**)&p_kk, g_kk);
    cudaGetSymbolAddress((void**)&p_y, g_y);
    cudaGetSymbolAddress((void**)&p_z, g_z);

    pack_B<<<Nfused,512>>>(q_w, k_w, v_w, w1, a1, v1, g1, q_b, k_b, v_b,
                           p_bigB, p_bigBias);
    // fused q|k|v|lora1 GEMM: [2048 x 2048] @ [3584 x 2048]^T
    gemm_nt_tf32<<<dim3(28,16),256>>>(x, p_bigB, p_bigBias, p_qkvh, Nfused, Cn);
    // LoRA stage-2 (A = h1 slice of fused output, lda = 3584)
    gemm_nn64 <<<dim3(32,32),256>>>(p_qkvh+3072+0,   Nfused, w2, Cn, w0,      p_wdec, Cn, Cn,  96, 1, 4);
    gemm_nn64 <<<dim3(32,32),256>>>(p_qkvh+3072+96,  Nfused, a2, Cn, a0,      p_iclr, Cn, Cn,  96, 0, 3);
    gemm_nn64 <<<dim3(32,32),256>>>(p_qkvh+3072+192, Nfused, v2, Cn, v0,      p_vsig, Cn, Cn,  64, 0, 3);
    gemm_nn64 <<<dim3(32,32),256>>>(p_qkvh+3072+256, Nfused, g2, Cn, nullptr, p_gate, Cn, Cn, 256, 2, 0);
    prep_kernel<<<8192,256>>>(p_qkvh, p_iclr, p_vsig, v_first, cosb, sinb,
                              k_k, k_a, p_rrot, p_kk, p_kfin, p_vfin);
    scan_kernel<<<128,128>>>(p_wdec, p_kk, p_iclr, p_kfin, p_vfin, p_rrot,
                             wkv_in, p_y, s_out);
    post_kernel<<<8192,256>>>(p_y, p_rrot, p_kfin, p_vfin, p_gate, r_k, ln_w, ln_b, p_z);
    gemm_nt_tf32<<<dim3(16,16),256>>>(p_z, o_w, nullptr, out, Cn, Cn);
    cudaMemcpyAsync(vf_out, v_first, (size_t)Tn*Cn*sizeof(float),
                    cudaMemcpyDeviceToDevice, 0);
}

// round 6
// speedup vs baseline: 1.9099x; 1.1941x over previous
#include <cuda_runtime.h>
#include <cuda_bf16.h>
#include <math.h>

#define Tn   2048
#define Cn   2048
#define Nfused 3584

// scratch (device globals zero-initialized; scanned streams padded +8 rows for ring prefetch)
__device__ float g_bigB[Nfused*Cn];
__device__ float g_bigBias[Nfused];
__device__ float g_qkvh[Tn*Nfused];
__device__ float g_wdec[(Tn+8)*Cn];
__device__ float g_iclr[(Tn+8)*Cn];
__device__ float g_vsig[Tn*Cn];
__device__ float g_gate[Tn*Cn];
__device__ float g_rrot[(Tn+8)*Cn];
__device__ float g_kfin[(Tn+8)*Cn];
__device__ float g_vfin[(Tn+8)*Cn];
__device__ float g_kk  [(Tn+8)*Cn];
__device__ float g_y[Tn*Cn];
__device__ float g_z[Tn*Cn];

__device__ __forceinline__ float sigf(float x){ return 1.0f/(1.0f + expf(-x)); }
__device__ __forceinline__ float decay_fn(float v){
    float nv = -v;
    float sp = (nv > 20.0f) ? nv : log1pf(expf(nv));
    return expf(-expf(-sp - 0.5f));
}
__device__ __forceinline__ unsigned f2tf32(float f){
    unsigned u;
    asm("cvt.rna.tf32.f32 %0, %1;" : "=r"(u) : "f"(f));
    return u;
}

#define CP16(sm, gp) asm volatile("cp.async.cg.shared.global [%0], [%1], 16;\n" :: "r"(sm), "l"(gp) : "memory")
#define CPCOMMIT()   asm volatile("cp.async.commit_group;\n" ::)
#define CPWAIT(n)    asm volatile("cp.async.wait_group %0;\n" :: "n"(n) : "memory")

// swizzled smem index for the GEMM: 16-word rows, conflict-free fragment access
__device__ __forceinline__ int SW(int row, int col){
    return row*16 + (col ^ (4*((row>>1)&3)));
}

// ---------------- pipelined TF32 tensor-core GEMM: C[M,N] = A[M,K] @ B[N,K]^T + bias ----------------
__global__ __launch_bounds__(256) void gemm_nt_tf32(
    const float* __restrict__ A, const float* __restrict__ B,
    const float* __restrict__ bias, float* __restrict__ C, int N, int K)
{
    __shared__ float As[3][128*16];
    __shared__ float Bs[3][128*16];
    const int m0 = blockIdx.y*128, n0 = blockIdx.x*128;
    const int tid = threadIdx.x;
    const int wid = tid>>5, lane = tid&31;
    const int wm = (wid>>1)*32, wn = (wid&1)*64;
    const int r = lane>>2, q = lane&3;

    const int row0 = tid>>2, c40 = (tid&3)*4;
    const int row1 = row0 + 64;
    const float* Ag = A + (size_t)m0*K;
    const float* Bg = B + (size_t)n0*K;
    const size_t a0off = (size_t)row0*K + c40;
    const size_t a1off = (size_t)row1*K + c40;

    float acc[2][8][4];
    #pragma unroll
    for (int i=0;i<2;i++)
        #pragma unroll
        for (int j=0;j<8;j++)
            #pragma unroll
            for (int c=0;c<4;c++) acc[i][j][c]=0.f;

    const int niter = K/16;
    #pragma unroll
    for (int p=0;p<2;p++){
        unsigned sa = (unsigned)__cvta_generic_to_shared(&As[p][0]);
        unsigned sb = (unsigned)__cvta_generic_to_shared(&Bs[p][0]);
        const float* ag = Ag + p*16;
        const float* bg = Bg + p*16;
        CP16(sa + SW(row0,c40)*4, ag + a0off);
        CP16(sa + SW(row1,c40)*4, ag + a1off);
        CP16(sb + SW(row0,c40)*4, bg + a0off);
        CP16(sb + SW(row1,c40)*4, bg + a1off);
        CPCOMMIT();
    }

    for (int it=0; it<niter; it++){
        const int nx = it+2;
        if (nx < niter){
            const int buf = nx%3;
            unsigned sa = (unsigned)__cvta_generic_to_shared(&As[buf][0]);
            unsigned sb = (unsigned)__cvta_generic_to_shared(&Bs[buf][0]);
            const float* ag = Ag + nx*16;
            const float* bg = Bg + nx*16;
            CP16(sa + SW(row0,c40)*4, ag + a0off);
            CP16(sa + SW(row1,c40)*4, ag + a1off);
            CP16(sb + SW(row0,c40)*4, bg + a0off);
            CP16(sb + SW(row1,c40)*4, bg + a1off);
        }
        CPCOMMIT();
        CPWAIT(2);
        __syncthreads();
        const float* as = As[it%3];
        const float* bs = Bs[it%3];
        #pragma unroll
        for (int ks=0; ks<2; ks++){
            const int kk = ks*8;
            unsigned a[2][4], b[8][2];
            #pragma unroll
            for (int mt=0;mt<2;mt++){
                const int row = wm + mt*16;
                a[mt][0]=f2tf32(as[SW(row+r,  kk+q  )]);
                a[mt][1]=f2tf32(as[SW(row+r+8,kk+q  )]);
                a[mt][2]=f2tf32(as[SW(row+r,  kk+q+4)]);
                a[mt][3]=f2tf32(as[SW(row+r+8,kk+q+4)]);
            }
            #pragma unroll
            for (int nt=0;nt<8;nt++){
                const int col = wn + nt*8;
                b[nt][0]=f2tf32(bs[SW(col+r, kk+q  )]);
                b[nt][1]=f2tf32(bs[SW(col+r, kk+q+4)]);
            }
            #pragma unroll
            for (int mt=0;mt<2;mt++){
                #pragma unroll
                for (int nt=0;nt<8;nt++){
                    asm volatile(
                        "mma.sync.aligned.m16n8k8.row.col.f32.tf32.tf32.f32 "
                        "{%0,%1,%2,%3}, {%4,%5,%6,%7}, {%8,%9}, {%0,%1,%2,%3};"
                        : "+f"(acc[mt][nt][0]),"+f"(acc[mt][nt][1]),
                          "+f"(acc[mt][nt][2]),"+f"(acc[mt][nt][3])
                        : "r"(a[mt][0]),"r"(a[mt][1]),"r"(a[mt][2]),"r"(a[mt][3]),
                          "r"(b[nt][0]),"r"(b[nt][1]));
                }
            }
        }
        __syncthreads();
    }
    #pragma unroll
    for (int mt=0;mt<2;mt++){
        #pragma unroll
        for (int nt=0;nt<8;nt++){
            int row = m0 + wm + mt*16 + r;
            int col = n0 + wn + nt*8 + q*2;
            float bx=0.f, by=0.f;
            if (bias){ bx=bias[col]; by=bias[col+1]; }
            *(float2*)(C + (size_t)row*N + col) =
                make_float2(acc[mt][nt][0]+bx, acc[mt][nt][1]+by);
            *(float2*)(C + (size_t)(row+8)*N + col) =
                make_float2(acc[mt][nt][2]+bx, acc[mt][nt][3]+by);
        }
    }
}

// fused LoRA stage-2: two configs per launch, selected by blockIdx.z
// epi: 0 none, 3 sigmoid(c+bias), 4 decay(c+bias); actA: 0 none, 1 tanh, 2 sigmoid
__global__ __launch_bounds__(256) void gemm_lora2(
    const float* A0, const float* A1, const float* B0, const float* B1,
    const float* b0, const float* b1, float* C0, float* C1,
    int K0, int K1, int actA0, int actA1, int epi0, int epi1)
{
    const int z = blockIdx.z;
    const float* A  = z ? A1 : A0;
    const float* Bm = z ? B1 : B0;
    const float* bias = z ? b1 : b0;
    float* C = z ? C1 : C0;
    const int K = z ? K1 : K0;
    const int actA = z ? actA1 : actA0;
    const int epi  = z ? epi1 : epi0;
    const int lda = Nfused, ldb = Cn, ldc = Cn, N = Cn;

    __shared__ float As[16][64], Bs[16][64];
    const int m0 = blockIdx.y*64, n0 = blockIdx.x*64;
    const int tid = threadIdx.x, tx = tid & 15, ty = tid >> 4;
    const int alr = tid >> 2, alk = (tid & 3)*4;
    const int bkr = tid >> 4, bnq = (tid & 15)*4;
    float acc[4][4];
    #pragma unroll
    for (int i=0;i<4;i++){
        #pragma unroll
        for (int j=0;j<4;j++) acc[i][j]=0.f;
    }
    for (int kt=0; kt<K; kt+=16){
        float4 av = *(const float4*)(A + (size_t)(m0+alr)*lda + kt + alk);
        float4 bv = *(const float4*)(Bm + (size_t)(kt+bkr)*ldb + n0 + bnq);
        if (actA==1){ av.x=tanhf(av.x); av.y=tanhf(av.y); av.z=tanhf(av.z); av.w=tanhf(av.w); }
        else if (actA==2){ av.x=sigf(av.x); av.y=sigf(av.y); av.z=sigf(av.z); av.w=sigf(av.w); }
        __syncthreads();
        As[alk+0][alr]=av.x; As[alk+1][alr]=av.y; As[alk+2][alr]=av.z; As[alk+3][alr]=av.w;
        *(float4*)&Bs[bkr][bnq] = bv;
        __syncthreads();
        #pragma unroll
        for (int k=0;k<16;k++){
            float4 a4 = *(const float4*)&As[k][ty*4];
            float4 b4 = *(const float4*)&Bs[k][tx*4];
            float a[4]={a4.x,a4.y,a4.z,a4.w}, b[4]={b4.x,b4.y,b4.z,b4.w};
            #pragma unroll
            for (int i=0;i<4;i++){
                #pragma unroll
                for (int j=0;j<4;j++) acc[i][j]=fmaf(a[i],b[j],acc[i][j]);
            }
        }
    }
    const int n = n0 + tx*4;
    float bb[4]={0,0,0,0};
    if (bias){
        #pragma unroll
        for (int j=0;j<4;j++) bb[j]=bias[n+j];
    }
    #pragma unroll
    for (int ii=0; ii<4; ii++){
        int gm = m0 + ty*4 + ii;
        float o[4];
        #pragma unroll
        for (int j=0;j<4;j++){
            float c = acc[ii][j];
            if (epi==3)      c = sigf(c + bb[j]);
            else if (epi==4) c = decay_fn(c + bb[j]);
            o[j]=c;
        }
        *(float4*)(C + (size_t)gm*ldc + n) = make_float4(o[0],o[1],o[2],o[3]);
    }
}

// pack fused B = [q_w ; k_w ; v_w ; wcatT] rows, and fused bias
__global__ void pack_B(const float* __restrict__ q_w, const float* __restrict__ k_w,
                       const float* __restrict__ v_w,
                       const float* __restrict__ w1, const float* __restrict__ a1,
                       const float* __restrict__ v1, const float* __restrict__ g1,
                       const float* __restrict__ q_b, const float* __restrict__ k_b,
                       const float* __restrict__ v_b,
                       float* __restrict__ Bout, float* __restrict__ biasOut)
{
    int row = blockIdx.x;
    for (int col = threadIdx.x; col < Cn; col += blockDim.x){
        float v;
        if (row < 2048)       v = q_w[(size_t)row*Cn + col];
        else if (row < 2560)  v = k_w[(size_t)(row-2048)*Cn + col];
        else if (row < 3072)  v = v_w[(size_t)(row-2560)*Cn + col];
        else {
            int c = row - 3072;
            if      (c < 96)  v = w1[(size_t)col*96  + c];
            else if (c < 192) v = a1[(size_t)col*96  + (c-96)];
            else if (c < 256) v = v1[(size_t)col*64  + (c-192)];
            else              v = g1[(size_t)col*256 + (c-256)];
        }
        Bout[(size_t)row*Cn + col] = v;
    }
    if (threadIdx.x == 0){
        float bv = 0.f;
        if (row < 2048)      bv = q_b[row];
        else if (row < 2560) bv = k_b[row-2048];
        else if (row < 3072) bv = v_b[row-2560];
        biasOut[row] = bv;
    }
}

// rope r/k, GQA repeat, kk normalize, k_final, v_final  (reads fused qkvh buffer)
__global__ __launch_bounds__(256) void prep_kernel(
    const float* __restrict__ qkvh,
    const float* __restrict__ iclr, const float* __restrict__ vsig, const float* __restrict__ vfirst,
    const float* __restrict__ cosb, const float* __restrict__ sinb,
    const float* __restrict__ k_k, const float* __restrict__ k_a,
    float* __restrict__ rrot, float* __restrict__ kkout,
    float* __restrict__ kfin, float* __restrict__ vfin)
{
    int wid = (blockIdx.x*blockDim.x + threadIdx.x) >> 5;
    int l = threadIdx.x & 31;
    int t = wid >> 5, h = wid & 31;
    int d0 = l, d1 = l+32;
    float c0 = cosb[t*64+d0], c1 = cosb[t*64+d1];
    float s0 = sinb[t*64+d0], s1 = sinb[t*64+d1];
    int base = t*Cn + h*64;
    int rbase = t*Nfused + h*64;
    int kbase = t*Nfused + 2048 + (h>>2)*64;
    int vbase = t*Nfused + 2560 + (h>>2)*64;
    float r0 = qkvh[rbase+d0], r1 = qkvh[rbase+d1];
    rrot[base+d0] = r0*c0 - r1*s0;
    rrot[base+d1] = r1*c1 + r0*s1;
    float k0 = qkvh[kbase+d0], k1 = qkvh[kbase+d1];
    float kr0 = k0*c0 - k1*s0, kr1 = k1*c1 + k0*s1;
    float m0 = kr0 * k_k[h*64+d0], m1 = kr1 * k_k[h*64+d1];
    float ss = m0*m0 + m1*m1;
    #pragma unroll
    for (int o=16;o>0;o>>=1) ss += __shfl_xor_sync(0xffffffffu, ss, o);
    float inv = 1.0f / fmaxf(sqrtf(ss), 1e-12f);
    kkout[base+d0] = m0*inv; kkout[base+d1] = m1*inv;
    float ic0 = iclr[base+d0], ic1 = iclr[base+d1];
    kfin[base+d0] = kr0 * (1.0f + (ic0-1.0f)*k_a[h*64+d0]);
    kfin[base+d1] = kr1 * (1.0f + (ic1-1.0f)*k_a[h*64+d1]);
    float v0v = qkvh[vbase+d0], v1v = qkvh[vbase+d1];
    vfin[base+d0] = v0v + (vfirst[base+d0]-v0v)*vsig[base+d0];
    vfin[base+d1] = v1v + (vfirst[base+d1]-v1v)*vsig[base+d1];
}

// scan: 128 CTAs (4/head, 16 rows x 8 lanes), smem cp.async ring depth 8,
// decoupled scalar recurrence d' = U - d*Q
__global__ __launch_bounds__(128) void scan_kernel(
    const float* __restrict__ wdec, const float* __restrict__ kkb,
    const float* __restrict__ aic,  const float* __restrict__ kf,
    const float* __restrict__ vf,   const float* __restrict__ rr,
    const float* __restrict__ s_in, float* __restrict__ yout, float* __restrict__ s_out)
{
    __shared__ float ring[5*8*64 + 8*16];   // 5 streams x 8 slots x 64 cols, + vf 8 slots x 16 rows
    const int b = blockIdx.x, h = b >> 2, rbk = b & 3;
    const int tid = threadIdx.x, rl = tid >> 3, sub = tid & 7;
    const int i = rbk*16 + rl, cb = sub*8;
    const int voff = h*64 + i;

    // producer chunk assignment (84 chunks: 5 streams x 16 + vf x 4)
    const float* src = nullptr;
    int dbase = 0, smul = 64;
    if (tid < 80){
        int s = tid >> 4, col16 = (tid & 15)*4;
        const float* bases[5] = {wdec, kkb, aic, kf, rr};
        src = bases[s] + h*64 + col16;
        dbase = s*512 + col16;
        smul = 64;
    } else if (tid < 84){
        int j = tid - 80;
        src = vf + h*64 + rbk*16 + j*4;
        dbase = 5*512 + j*4;
        smul = 16;
    }
    const unsigned smbase = (unsigned)__cvta_generic_to_shared(ring);

    // prologue: fill slots 0..6
    for (int tt=0; tt<7; tt++){
        if (src) CP16(smbase + (dbase + tt*smul)*4, src + (size_t)tt*Cn);
        CPCOMMIT();
    }

    float S[8];
    {
        const float4* sp = (const float4*)(s_in + (size_t)(h*64 + i)*64 + cb);
        float4 a = sp[0], c = sp[1];
        S[0]=a.x;S[1]=a.y;S[2]=a.z;S[3]=a.w;S[4]=c.x;S[5]=c.y;S[6]=c.z;S[7]=c.w;
    }

    // initial d = S . kk_0
    CPWAIT(5);
    __syncthreads();
    float d;
    {
        const float* K0 = ring + 512 + cb;   // stream 1 slot 0
        float t0=0.f, t1=0.f;
        #pragma unroll
        for (int q2=0;q2<4;q2++){ t0 = fmaf(S[q2], K0[q2], t0); t1 = fmaf(S[q2+4], K0[q2+4], t1); }
        d = t0 + t1;
        d += __shfl_xor_sync(0xffffffffu, d, 1);
        d += __shfl_xor_sync(0xffffffffu, d, 2);
        d += __shfl_xor_sync(0xffffffffu, d, 4);
    }

    for (int t=0; t<Tn; t++){
        const int p = t & 7, pn = (t+1) & 7;
        CPWAIT(5);                      // slots t and t+1 ready
        __syncthreads();                // producers' data visible; last iter's reads done
        // prefetch t+7 into slot (t-1)&7 (freed by the barrier)
        if (src) CP16(smbase + (dbase + ((t+7)&7)*smul)*4, src + (size_t)(t+7)*Cn);
        CPCOMMIT();

        const float* W  = ring + 0*512 + p*64 + cb;
        const float* K  = ring + 1*512 + p*64 + cb;
        const float* A  = ring + 2*512 + p*64 + cb;
        const float* F  = ring + 3*512 + p*64 + cb;
        const float* R  = ring + 4*512 + p*64 + cb;
        const float* Kn = ring + 1*512 + pn*64 + cb;
        const float vi  = ring[5*512 + p*16 + rl];

        float4 w0=((const float4*)W)[0],  w1=((const float4*)W)[1];
        float4 k0=((const float4*)K)[0],  k1=((const float4*)K)[1];
        float4 a0=((const float4*)A)[0],  a1=((const float4*)A)[1];
        float4 f0=((const float4*)F)[0],  f1=((const float4*)F)[1];
        float4 r0=((const float4*)R)[0],  r1=((const float4*)R)[1];
        float4 n0=((const float4*)Kn)[0], n1=((const float4*)Kn)[1];
        float w[8]={w0.x,w0.y,w0.z,w0.w,w1.x,w1.y,w1.z,w1.w};
        float kv[8]={k0.x,k0.y,k0.z,k0.w,k1.x,k1.y,k1.z,k1.w};
        float av[8]={a0.x,a0.y,a0.z,a0.w,a1.x,a1.y,a1.z,a1.w};
        float fv[8]={f0.x,f0.y,f0.z,f0.w,f1.x,f1.y,f1.z,f1.w};
        float rv[8]={r0.x,r0.y,r0.z,r0.w,r1.x,r1.y,r1.z,r1.w};
        float kn[8]={n0.x,n0.y,n0.z,n0.w,n1.x,n1.y,n1.z,n1.w};

        float u[8], ab[8];
        float Ul0=0.f, Ul1=0.f, Ql0=0.f, Ql1=0.f;
        #pragma unroll
        for (int q2=0;q2<8;q2++){
            ab[q2] = kv[q2]*av[q2];
            u[q2]  = fmaf(S[q2], w[q2], vi*fv[q2]);
            if (q2<4){ Ul0 = fmaf(u[q2], kn[q2], Ul0); Ql0 = fmaf(ab[q2], kn[q2], Ql0); }
            else     { Ul1 = fmaf(u[q2], kn[q2], Ul1); Ql1 = fmaf(ab[q2], kn[q2], Ql1); }
        }
        float U = Ul0 + Ul1, Q = Ql0 + Ql1;
        U += __shfl_xor_sync(0xffffffffu, U, 1);
        Q += __shfl_xor_sync(0xffffffffu, Q, 1);
        U += __shfl_xor_sync(0xffffffffu, U, 2);
        Q += __shfl_xor_sync(0xffffffffu, Q, 2);
        U += __shfl_xor_sync(0xffffffffu, U, 4);
        Q += __shfl_xor_sync(0xffffffffu, Q, 4);

        float y0=0.f, y1=0.f;
        #pragma unroll
        for (int q2=0;q2<8;q2++){
            S[q2] = fmaf(-d, ab[q2], u[q2]);
            if (q2<4) y0 = fmaf(S[q2], rv[q2], y0); else y1 = fmaf(S[q2], rv[q2], y1);
        }
        float yv = y0 + y1;
        yv += __shfl_xor_sync(0xffffffffu, yv, 1);
        yv += __shfl_xor_sync(0xffffffffu, yv, 2);
        yv += __shfl_xor_sync(0xffffffffu, yv, 4);
        if (sub==0) yout[(size_t)t*Cn + voff] = yv;

        d = fmaf(-d, Q, U);   // d_{t+1}
    }
    float4* so = (float4*)(s_out + (size_t)(h*64+i)*64 + cb);
    so[0] = make_float4(S[0],S[1],S[2],S[3]);
    so[1] = make_float4(S[4],S[5],S[6],S[7]);
}

// groupnorm + ln + bonus + gate
__global__ __launch_bounds__(256) void post_kernel(
    const float* __restrict__ y, const float* __restrict__ rrot,
    const float* __restrict__ kfin, const float* __restrict__ vfin,
    const float* __restrict__ gate, const float* __restrict__ r_k,
    const float* __restrict__ ln_w, const float* __restrict__ ln_b,
    float* __restrict__ z)
{
    int wid = (blockIdx.x*blockDim.x + threadIdx.x) >> 5;
    int l = threadIdx.x & 31;
    int t = wid >> 5, h = wid & 31;
    int base = t*Cn + h*64;
    int d0 = l, d1 = l+32;
    float y0 = y[base+d0], y1 = y[base+d1];
    float s = y0+y1, sq = y0*y0 + y1*y1;
    float r0 = rrot[base+d0], r1 = rrot[base+d1];
    float dot = r0*kfin[base+d0]*r_k[h*64+d0] + r1*kfin[base+d1]*r_k[h*64+d1];
    #pragma unroll
    for (int o=16;o>0;o>>=1){
        s   += __shfl_xor_sync(0xffffffffu, s, o);
        sq  += __shfl_xor_sync(0xffffffffu, sq, o);
        dot += __shfl_xor_sync(0xffffffffu, dot, o);
    }
    float mu = s * (1.0f/64.0f);
    float var = sq * (1.0f/64.0f) - mu*mu;
    float rstd = rsqrtf(var + 6.4e-4f);
    float n0 = (y0-mu)*rstd*ln_w[h*64+d0] + ln_b[h*64+d0];
    float n1 = (y1-mu)*rstd*ln_w[h*64+d1] + ln_b[h*64+d1];
    z[base+d0] = (n0 + dot*vfin[base+d0]) * gate[base+d0];
    z[base+d1] = (n1 + dot*vfin[base+d1]) * gate[base+d1];
}

extern "C" void kernel_launch(void* const* d_in, const int* in_sizes, int n_in,
                              void* d_out, int out_size) {
    const float* x       = (const float*)d_in[0];
    const float* wkv_in  = (const float*)d_in[1];
    const float* v_first = (const float*)d_in[2];
    const float* cosb    = (const float*)d_in[3];
    const float* sinb    = (const float*)d_in[4];
    const float* w0      = (const float*)d_in[5];
    const float* w1      = (const float*)d_in[6];
    const float* w2      = (const float*)d_in[7];
    const float* a0      = (const float*)d_in[8];
    const float* a1      = (const float*)d_in[9];
    const float* a2      = (const float*)d_in[10];
    const float* v0      = (const float*)d_in[11];
    const float* v1      = (const float*)d_in[12];
    const float* v2      = (const float*)d_in[13];
    const float* g1      = (const float*)d_in[14];
    const float* g2      = (const float*)d_in[15];
    const float* k_k     = (const float*)d_in[16];
    const float* k_a     = (const float*)d_in[17];
    const float* r_k     = (const float*)d_in[18];
    const float* q_w     = (const float*)d_in[19];
    const float* q_b     = (const float*)d_in[20];
    const float* k_w     = (const float*)d_in[21];
    const float* k_b     = (const float*)d_in[22];
    const float* v_w     = (const float*)d_in[23];
    const float* v_b     = (const float*)d_in[24];
    const float* o_w     = (const float*)d_in[25];
    const float* ln_w    = (const float*)d_in[26];
    const float* ln_b    = (const float*)d_in[27];

    float* out   = (float*)d_out;
    float* s_out = out + (size_t)Tn*Cn;
    float* vf_out = s_out + 32*64*64;

    float *p_bigB, *p_bigBias, *p_qkvh, *p_wdec, *p_iclr, *p_vsig, *p_gate;
    float *p_rrot, *p_kfin, *p_vfin, *p_kk, *p_y, *p_z;
    cudaGetSymbolAddress((void**)&p_bigB, g_bigB);
    cudaGetSymbolAddress((void**)&p_bigBias, g_bigBias);
    cudaGetSymbolAddress((void**)&p_qkvh, g_qkvh);
    cudaGetSymbolAddress((void**)&p_wdec, g_wdec);
    cudaGetSymbolAddress((void**)&p_iclr, g_iclr);
    cudaGetSymbolAddress((void**)&p_vsig, g_vsig);
    cudaGetSymbolAddress((void**)&p_gate, g_gate);
    cudaGetSymbolAddress((void**)&p_rrot, g_rrot);
    cudaGetSymbolAddress((void**)&p_kfin, g_kfin);
    cudaGetSymbolAddress((void**)&p_vfin, g_vfin);
    cudaGetSymbolAddress((void**)&p_kk, g_kk);
    cudaGetSymbolAddress((void**)&p_y, g_y);
    cudaGetSymbolAddress((void**)&p_z, g_z);

    pack_B<<<Nfused,512>>>(q_w, k_w, v_w, w1, a1, v1, g1, q_b, k_b, v_b,
                           p_bigB, p_bigBias);
    gemm_nt_tf32<<<dim3(28,16),256>>>(x, p_bigB, p_bigBias, p_qkvh, Nfused, Cn);
    // LoRA stage-2 fused pairs
    gemm_lora2<<<dim3(32,32,2),256>>>(p_qkvh+3072+0, p_qkvh+3072+96, w2, a2,
                                      w0, a0, p_wdec, p_iclr, 96, 96, 1, 0, 4, 3);
    gemm_lora2<<<dim3(32,32,2),256>>>(p_qkvh+3072+192, p_qkvh+3072+256, v2, g2,
                                      v0, nullptr, p_vsig, p_gate, 64, 256, 0, 2, 3, 0);
    prep_kernel<<<8192,256>>>(p_qkvh, p_iclr, p_vsig, v_first, cosb, sinb,
                              k_k, k_a, p_rrot, p_kk, p_kfin, p_vfin);
    scan_kernel<<<128,128>>>(p_wdec, p_kk, p_iclr, p_kfin, p_vfin, p_rrot,
                             wkv_in, p_y, s_out);
    post_kernel<<<8192,256>>>(p_y, p_rrot, p_kfin, p_vfin, p_gate, r_k, ln_w, ln_b, p_z);
    gemm_nt_tf32<<<dim3(16,16),256>>>(p_z, o_w, nullptr, out, Cn, Cn);
    cudaMemcpyAsync(vf_out, v_first, (size_t)Tn*Cn*sizeof(float),
                    cudaMemcpyDeviceToDevice, 0);
}

// round 7
// speedup vs baseline: 1.9957x; 1.0449x over previous
#include <cuda_runtime.h>
#include <cuda_bf16.h>
#include <math.h>

#define Tn   2048
#define Cn   2048
#define Nfused 3584

#define OFF_W 0
#define OFF_A (2048*96)
#define OFF_V (OFF_A + 2048*96)
#define OFF_G (OFF_V + 2048*64)

// scratch (device globals zero-initialized; scanned streams padded +8 rows for ring prefetch)
__device__ float g_bigB[Nfused*Cn];
__device__ float g_bigBias[Nfused];
__device__ float g_B2[2048*512];
__device__ float g_h1act[Tn*384];
__device__ float g_qkvh[Tn*Nfused];
__device__ float g_wdec[(Tn+8)*Cn];
__device__ float g_iclr[(Tn+8)*Cn];
__device__ float g_vsig[Tn*Cn];
__device__ float g_gate[Tn*Cn];
__device__ float g_rrot[(Tn+8)*Cn];
__device__ float g_kfin[(Tn+8)*Cn];
__device__ float g_vfin[(Tn+8)*Cn];
__device__ float g_kk  [(Tn+8)*Cn];
__device__ float g_y[Tn*Cn];
__device__ float g_z[Tn*Cn];

__device__ __forceinline__ float sigf(float x){ return 1.0f/(1.0f + expf(-x)); }
__device__ __forceinline__ float decay_fn(float v){
    float nv = -v;
    float sp = (nv > 20.0f) ? nv : log1pf(expf(nv));
    return expf(-expf(-sp - 0.5f));
}
__device__ __forceinline__ unsigned f2tf32(float f){
    unsigned u;
    asm("cvt.rna.tf32.f32 %0, %1;" : "=r"(u) : "f"(f));
    return u;
}

#define CP16(sm, gp) asm volatile("cp.async.cg.shared.global [%0], [%1], 16;\n" :: "r"(sm), "l"(gp) : "memory")
#define CPCOMMIT()   asm volatile("cp.async.commit_group;\n" ::)
#define CPWAIT(n)    asm volatile("cp.async.wait_group %0;\n" :: "n"(n) : "memory")

__device__ __forceinline__ int SW(int row, int col){
    return row*16 + (col ^ (4*((row>>1)&3)));
}

// ---------------- pipelined TF32 GEMM: C[M,N] = A[M,K](lda) @ B[N,K]^T + bias, epilogue ----------------
// epi: 0 none, 3 sigmoid(c+bias), 4 decay(c+bias)
__global__ __launch_bounds__(256) void gemm_nt_tf32(
    const float* __restrict__ A, int lda, const float* __restrict__ B,
    const float* __restrict__ bias, float* __restrict__ C, int N, int K, int epi)
{
    __shared__ float As[3][128*16];
    __shared__ float Bs[3][128*16];
    const int m0 = blockIdx.y*128, n0 = blockIdx.x*128;
    const int tid = threadIdx.x;
    const int wid = tid>>5, lane = tid&31;
    const int wm = (wid>>1)*32, wn = (wid&1)*64;
    const int r = lane>>2, q = lane&3;

    const int row0 = tid>>2, c40 = (tid&3)*4;
    const int row1 = row0 + 64;
    const float* Ag = A + (size_t)m0*lda;
    const float* Bg = B + (size_t)n0*K;
    const size_t a0off = (size_t)row0*lda + c40;
    const size_t a1off = (size_t)row1*lda + c40;
    const size_t b0off = (size_t)row0*K + c40;
    const size_t b1off = (size_t)row1*K + c40;

    float acc[2][8][4];
    #pragma unroll
    for (int i=0;i<2;i++)
        #pragma unroll
        for (int j=0;j<8;j++)
            #pragma unroll
            for (int c=0;c<4;c++) acc[i][j][c]=0.f;

    const int niter = K/16;
    #pragma unroll
    for (int p=0;p<2;p++){
        unsigned sa = (unsigned)__cvta_generic_to_shared(&As[p][0]);
        unsigned sb = (unsigned)__cvta_generic_to_shared(&Bs[p][0]);
        CP16(sa + SW(row0,c40)*4, Ag + p*16 + a0off);
        CP16(sa + SW(row1,c40)*4, Ag + p*16 + a1off);
        CP16(sb + SW(row0,c40)*4, Bg + p*16 + b0off);
        CP16(sb + SW(row1,c40)*4, Bg + p*16 + b1off);
        CPCOMMIT();
    }

    for (int it=0; it<niter; it++){
        const int nx = it+2;
        if (nx < niter){
            const int buf = nx%3;
            unsigned sa = (unsigned)__cvta_generic_to_shared(&As[buf][0]);
            unsigned sb = (unsigned)__cvta_generic_to_shared(&Bs[buf][0]);
            CP16(sa + SW(row0,c40)*4, Ag + nx*16 + a0off);
            CP16(sa + SW(row1,c40)*4, Ag + nx*16 + a1off);
            CP16(sb + SW(row0,c40)*4, Bg + nx*16 + b0off);
            CP16(sb + SW(row1,c40)*4, Bg + nx*16 + b1off);
        }
        CPCOMMIT();
        CPWAIT(2);
        __syncthreads();
        const float* as = As[it%3];
        const float* bs = Bs[it%3];
        #pragma unroll
        for (int ks=0; ks<2; ks++){
            const int kk = ks*8;
            unsigned a[2][4], b[8][2];
            #pragma unroll
            for (int mt=0;mt<2;mt++){
                const int row = wm + mt*16;
                a[mt][0]=f2tf32(as[SW(row+r,  kk+q  )]);
                a[mt][1]=f2tf32(as[SW(row+r+8,kk+q  )]);
                a[mt][2]=f2tf32(as[SW(row+r,  kk+q+4)]);
                a[mt][3]=f2tf32(as[SW(row+r+8,kk+q+4)]);
            }
            #pragma unroll
            for (int nt=0;nt<8;nt++){
                const int col = wn + nt*8;
                b[nt][0]=f2tf32(bs[SW(col+r, kk+q  )]);
                b[nt][1]=f2tf32(bs[SW(col+r, kk+q+4)]);
            }
            #pragma unroll
            for (int mt=0;mt<2;mt++){
                #pragma unroll
                for (int nt=0;nt<8;nt++){
                    asm volatile(
                        "mma.sync.aligned.m16n8k8.row.col.f32.tf32.tf32.f32 "
                        "{%0,%1,%2,%3}, {%4,%5,%6,%7}, {%8,%9}, {%0,%1,%2,%3};"
                        : "+f"(acc[mt][nt][0]),"+f"(acc[mt][nt][1]),
                          "+f"(acc[mt][nt][2]),"+f"(acc[mt][nt][3])
                        : "r"(a[mt][0]),"r"(a[mt][1]),"r"(a[mt][2]),"r"(a[mt][3]),
                          "r"(b[nt][0]),"r"(b[nt][1]));
                }
            }
        }
        __syncthreads();
    }
    #pragma unroll
    for (int mt=0;mt<2;mt++){
        #pragma unroll
        for (int nt=0;nt<8;nt++){
            int row = m0 + wm + mt*16 + r;
            int col = n0 + wn + nt*8 + q*2;
            float bx=0.f, by=0.f;
            if (bias){ bx=bias[col]; by=bias[col+1]; }
            float o00=acc[mt][nt][0]+bx, o01=acc[mt][nt][1]+by;
            float o10=acc[mt][nt][2]+bx, o11=acc[mt][nt][3]+by;
            if (epi==3){ o00=sigf(o00); o01=sigf(o01); o10=sigf(o10); o11=sigf(o11); }
            else if (epi==4){ o00=decay_fn(o00); o01=decay_fn(o01); o10=decay_fn(o10); o11=decay_fn(o11); }
            *(float2*)(C + (size_t)row*N + col)     = make_float2(o00,o01);
            *(float2*)(C + (size_t)(row+8)*N + col) = make_float2(o10,o11);
        }
    }
}

// pack fused B = [q_w ; k_w ; v_w ; wcatT] rows, and fused bias
__global__ void pack_B(const float* __restrict__ q_w, const float* __restrict__ k_w,
                       const float* __restrict__ v_w,
                       const float* __restrict__ w1, const float* __restrict__ a1,
                       const float* __restrict__ v1, const float* __restrict__ g1,
                       const float* __restrict__ q_b, const float* __restrict__ k_b,
                       const float* __restrict__ v_b,
                       float* __restrict__ Bout, float* __restrict__ biasOut)
{
    int row = blockIdx.x;
    for (int col = threadIdx.x; col < Cn; col += blockDim.x){
        float v;
        if (row < 2048)       v = q_w[(size_t)row*Cn + col];
        else if (row < 2560)  v = k_w[(size_t)(row-2048)*Cn + col];
        else if (row < 3072)  v = v_w[(size_t)(row-2560)*Cn + col];
        else {
            int c = row - 3072;
            if      (c < 96)  v = w1[(size_t)col*96  + c];
            else if (c < 192) v = a1[(size_t)col*96  + (c-96)];
            else if (c < 256) v = v1[(size_t)col*64  + (c-192)];
            else              v = g1[(size_t)col*256 + (c-256)];
        }
        Bout[(size_t)row*Cn + col] = v;
    }
    if (threadIdx.x == 0){
        float bv = 0.f;
        if (row < 2048)      bv = q_b[row];
        else if (row < 2560) bv = k_b[row-2048];
        else if (row < 3072) bv = v_b[row-2560];
        biasOut[row] = bv;
    }
}

// transpose-pack stage-2 weights: [K,2048] -> [2048,K]
__global__ void pack_T2(const float* __restrict__ w2, const float* __restrict__ a2,
                        const float* __restrict__ v2, const float* __restrict__ g2,
                        float* __restrict__ out)
{
    int n = blockIdx.x, which = blockIdx.y, k = threadIdx.x;
    if (which==0){ if (k<96)  out[OFF_W + (size_t)n*96  + k] = w2[(size_t)k*Cn + n]; }
    else if (which==1){ if (k<96)  out[OFF_A + (size_t)n*96  + k] = a2[(size_t)k*Cn + n]; }
    else if (which==2){ if (k<64)  out[OFF_V + (size_t)n*64  + k] = v2[(size_t)k*Cn + n]; }
    else              { if (k<256) out[OFF_G + (size_t)n*256 + k] = g2[(size_t)k*Cn + n]; }
}

// activate h1 slices: cols 0..95 = tanh(w-slice), 96..351 = sigmoid(g-slice)
__global__ void h1act_kernel(const float* __restrict__ qkvh, float* __restrict__ out)
{
    int row = blockIdx.x, c = threadIdx.x;
    if (c < 96)       out[(size_t)row*384 + c] = tanhf(qkvh[(size_t)row*Nfused + 3072 + c]);
    else if (c < 352) out[(size_t)row*384 + c] = sigf(qkvh[(size_t)row*Nfused + 3072 + 256 + (c-96)]);
}

// rope r/k, GQA repeat, kk normalize, k_final, v_final
__global__ __launch_bounds__(256) void prep_kernel(
    const float* __restrict__ qkvh,
    const float* __restrict__ iclr, const float* __restrict__ vsig, const float* __restrict__ vfirst,
    const float* __restrict__ cosb, const float* __restrict__ sinb,
    const float* __restrict__ k_k, const float* __restrict__ k_a,
    float* __restrict__ rrot, float* __restrict__ kkout,
    float* __restrict__ kfin, float* __restrict__ vfin)
{
    int wid = (blockIdx.x*blockDim.x + threadIdx.x) >> 5;
    int l = threadIdx.x & 31;
    int t = wid >> 5, h = wid & 31;
    int d0 = l, d1 = l+32;
    float c0 = cosb[t*64+d0], c1 = cosb[t*64+d1];
    float s0 = sinb[t*64+d0], s1 = sinb[t*64+d1];
    int base = t*Cn + h*64;
    int rbase = t*Nfused + h*64;
    int kbase = t*Nfused + 2048 + (h>>2)*64;
    int vbase = t*Nfused + 2560 + (h>>2)*64;
    float r0 = qkvh[rbase+d0], r1 = qkvh[rbase+d1];
    rrot[base+d0] = r0*c0 - r1*s0;
    rrot[base+d1] = r1*c1 + r0*s1;
    float k0 = qkvh[kbase+d0], k1 = qkvh[kbase+d1];
    float kr0 = k0*c0 - k1*s0, kr1 = k1*c1 + k0*s1;
    float m0 = kr0 * k_k[h*64+d0], m1 = kr1 * k_k[h*64+d1];
    float ss = m0*m0 + m1*m1;
    #pragma unroll
    for (int o=16;o>0;o>>=1) ss += __shfl_xor_sync(0xffffffffu, ss, o);
    float inv = 1.0f / fmaxf(sqrtf(ss), 1e-12f);
    kkout[base+d0] = m0*inv; kkout[base+d1] = m1*inv;
    float ic0 = iclr[base+d0], ic1 = iclr[base+d1];
    kfin[base+d0] = kr0 * (1.0f + (ic0-1.0f)*k_a[h*64+d0]);
    kfin[base+d1] = kr1 * (1.0f + (ic1-1.0f)*k_a[h*64+d1]);
    float v0v = qkvh[vbase+d0], v1v = qkvh[vbase+d1];
    vfin[base+d0] = v0v + (vfirst[base+d0]-v0v)*vsig[base+d0];
    vfin[base+d1] = v1v + (vfirst[base+d1]-v1v)*vsig[base+d1];
}

// scan v2: smem ring + fully decoupled recurrence (d-chain = 1 FMA/step).
// state: u_t = S_t + d_t*ab_t ; S_{t-1} = u_{t-1} - d_{t-1}*ab_{t-1}
__global__ __launch_bounds__(128) void scan_kernel(
    const float* __restrict__ wdec, const float* __restrict__ kkb,
    const float* __restrict__ aic,  const float* __restrict__ kf,
    const float* __restrict__ vf,   const float* __restrict__ rr,
    const float* __restrict__ s_in, float* __restrict__ yout, float* __restrict__ s_out)
{
    __shared__ float ring[5*8*64 + 8*16];
    const int b = blockIdx.x, h = b >> 2, rbk = b & 3;
    const int tid = threadIdx.x, rl = tid >> 3, sub = tid & 7;
    const int i = rbk*16 + rl, cb = sub*8;
    const int voff = h*64 + i;

    const float* src = nullptr;
    int dbase = 0, smul = 64;
    if (tid < 80){
        int s = tid >> 4, col16 = (tid & 15)*4;
        const float* bases[5] = {wdec, kkb, aic, kf, rr};
        src = bases[s] + h*64 + col16;
        dbase = s*512 + col16;
        smul = 64;
    } else if (tid < 84){
        int j = tid - 80;
        src = vf + h*64 + rbk*16 + j*4;
        dbase = 5*512 + j*4;
        smul = 16;
    }
    const unsigned smbase = (unsigned)__cvta_generic_to_shared(ring);

    for (int tt=0; tt<7; tt++){
        if (src) CP16(smbase + (dbase + tt*smul)*4, src + (size_t)tt*Cn);
        CPCOMMIT();
    }

    float u[8], ab[8];
    {
        const float4* sp = (const float4*)(s_in + (size_t)(h*64 + i)*64 + cb);
        float4 a = sp[0], c = sp[1];
        u[0]=a.x;u[1]=a.y;u[2]=a.z;u[3]=a.w;u[4]=c.x;u[5]=c.y;u[6]=c.z;u[7]=c.w;
    }
    #pragma unroll
    for (int q2=0;q2<8;q2++) ab[q2]=0.f;

    CPWAIT(5);
    __syncthreads();
    float d_prev = 0.f, d_cur;
    {
        const float* K0 = ring + 512 + cb;
        float t0=0.f, t1=0.f;
        #pragma unroll
        for (int q2=0;q2<4;q2++){ t0 = fmaf(u[q2], K0[q2], t0); t1 = fmaf(u[q2+4], K0[q2+4], t1); }
        d_cur = t0 + t1;
        d_cur += __shfl_xor_sync(0xffffffffu, d_cur, 1);
        d_cur += __shfl_xor_sync(0xffffffffu, d_cur, 2);
        d_cur += __shfl_xor_sync(0xffffffffu, d_cur, 4);
    }

    #pragma unroll 2
    for (int t=0; t<Tn; t++){
        const int p = t & 7, pn = (t+1) & 7;
        CPWAIT(5);
        __syncthreads();
        if (src) CP16(smbase + (dbase + ((t+7)&7)*smul)*4, src + (size_t)(t+7)*Cn);
        CPCOMMIT();

        const float* W  = ring + 0*512 + p*64 + cb;
        const float* K  = ring + 1*512 + p*64 + cb;
        const float* A  = ring + 2*512 + p*64 + cb;
        const float* F  = ring + 3*512 + p*64 + cb;
        const float* R  = ring + 4*512 + p*64 + cb;
        const float* Kn = ring + 1*512 + pn*64 + cb;
        const float vi  = ring[5*512 + p*16 + rl];

        float4 w0=((const float4*)W)[0],  w1=((const float4*)W)[1];
        float4 k0=((const float4*)K)[0],  k1=((const float4*)K)[1];
        float4 a0=((const float4*)A)[0],  a1=((const float4*)A)[1];
        float4 f0=((const float4*)F)[0],  f1=((const float4*)F)[1];
        float4 r0=((const float4*)R)[0],  r1=((const float4*)R)[1];
        float4 n0=((const float4*)Kn)[0], n1=((const float4*)Kn)[1];
        float w[8]={w0.x,w0.y,w0.z,w0.w,w1.x,w1.y,w1.z,w1.w};
        float kv[8]={k0.x,k0.y,k0.z,k0.w,k1.x,k1.y,k1.z,k1.w};
        float av[8]={a0.x,a0.y,a0.z,a0.w,a1.x,a1.y,a1.z,a1.w};
        float fv[8]={f0.x,f0.y,f0.z,f0.w,f1.x,f1.y,f1.z,f1.w};
        float rv[8]={r0.x,r0.y,r0.z,r0.w,r1.x,r1.y,r1.z,r1.w};
        float kn[8]={n0.x,n0.y,n0.z,n0.w,n1.x,n1.y,n1.z,n1.w};

        float Ul0=0.f,Ul1=0.f,Ql0=0.f,Ql1=0.f,R1l0=0.f,R1l1=0.f,R2l0=0.f,R2l1=0.f;
        float un[8], abn[8];
        #pragma unroll
        for (int q2=0;q2<8;q2++){
            float sprev = fmaf(-d_prev, ab[q2], u[q2]);       // S_{t-1}
            un[q2]  = fmaf(vi, fv[q2], sprev*w[q2]);          // u_t
            abn[q2] = kv[q2]*av[q2];                          // ab_t
            if (q2<4){
                Ul0 = fmaf(un[q2], kn[q2], Ul0);  Ql0 = fmaf(abn[q2], kn[q2], Ql0);
                R1l0= fmaf(un[q2], rv[q2], R1l0); R2l0= fmaf(abn[q2], rv[q2], R2l0);
            } else {
                Ul1 = fmaf(un[q2], kn[q2], Ul1);  Ql1 = fmaf(abn[q2], kn[q2], Ql1);
                R1l1= fmaf(un[q2], rv[q2], R1l1); R2l1= fmaf(abn[q2], rv[q2], R2l1);
            }
        }
        float U = Ul0+Ul1, Q = Ql0+Ql1, R1 = R1l0+R1l1, R2 = R2l0+R2l1;
        U  += __shfl_xor_sync(0xffffffffu, U, 1);
        Q  += __shfl_xor_sync(0xffffffffu, Q, 1);
        R1 += __shfl_xor_sync(0xffffffffu, R1, 1);
        R2 += __shfl_xor_sync(0xffffffffu, R2, 1);
        U  += __shfl_xor_sync(0xffffffffu, U, 2);
        Q  += __shfl_xor_sync(0xffffffffu, Q, 2);
        R1 += __shfl_xor_sync(0xffffffffu, R1, 2);
        R2 += __shfl_xor_sync(0xffffffffu, R2, 2);
        U  += __shfl_xor_sync(0xffffffffu, U, 4);
        Q  += __shfl_xor_sync(0xffffffffu, Q, 4);
        R1 += __shfl_xor_sync(0xffffffffu, R1, 4);
        R2 += __shfl_xor_sync(0xffffffffu, R2, 4);

        if (sub==0) yout[(size_t)t*Cn + voff] = fmaf(-d_cur, R2, R1);   // y_t = S_t . r_t

        #pragma unroll
        for (int q2=0;q2<8;q2++){ u[q2]=un[q2]; ab[q2]=abn[q2]; }
        d_prev = d_cur;
        d_cur  = fmaf(-d_cur, Q, U);   // d_{t+1}
    }
    // S_final = u_{T-1} - d_{T-1}*ab_{T-1}
    float4* so = (float4*)(s_out + (size_t)(h*64+i)*64 + cb);
    so[0] = make_float4(fmaf(-d_prev,ab[0],u[0]), fmaf(-d_prev,ab[1],u[1]),
                        fmaf(-d_prev,ab[2],u[2]), fmaf(-d_prev,ab[3],u[3]));
    so[1] = make_float4(fmaf(-d_prev,ab[4],u[4]), fmaf(-d_prev,ab[5],u[5]),
                        fmaf(-d_prev,ab[6],u[6]), fmaf(-d_prev,ab[7],u[7]));
}

// groupnorm + ln + bonus + gate
__global__ __launch_bounds__(256) void post_kernel(
    const float* __restrict__ y, const float* __restrict__ rrot,
    const float* __restrict__ kfin, const float* __restrict__ vfin,
    const float* __restrict__ gate, const float* __restrict__ r_k,
    const float* __restrict__ ln_w, const float* __restrict__ ln_b,
    float* __restrict__ z)
{
    int wid = (blockIdx.x*blockDim.x + threadIdx.x) >> 5;
    int l = threadIdx.x & 31;
    int t = wid >> 5, h = wid & 31;
    int base = t*Cn + h*64;
    int d0 = l, d1 = l+32;
    float y0 = y[base+d0], y1 = y[base+d1];
    float s = y0+y1, sq = y0*y0 + y1*y1;
    float r0 = rrot[base+d0], r1 = rrot[base+d1];
    float dot = r0*kfin[base+d0]*r_k[h*64+d0] + r1*kfin[base+d1]*r_k[h*64+d1];
    #pragma unroll
    for (int o=16;o>0;o>>=1){
        s   += __shfl_xor_sync(0xffffffffu, s, o);
        sq  += __shfl_xor_sync(0xffffffffu, sq, o);
        dot += __shfl_xor_sync(0xffffffffu, dot, o);
    }
    float mu = s * (1.0f/64.0f);
    float var = sq * (1.0f/64.0f) - mu*mu;
    float rstd = rsqrtf(var + 6.4e-4f);
    float n0 = (y0-mu)*rstd*ln_w[h*64+d0] + ln_b[h*64+d0];
    float n1 = (y1-mu)*rstd*ln_w[h*64+d1] + ln_b[h*64+d1];
    z[base+d0] = (n0 + dot*vfin[base+d0]) * gate[base+d0];
    z[base+d1] = (n1 + dot*vfin[base+d1]) * gate[base+d1];
}

extern "C" void kernel_launch(void* const* d_in, const int* in_sizes, int n_in,
                              void* d_out, int out_size) {
    const float* x       = (const float*)d_in[0];
    const float* wkv_in  = (const float*)d_in[1];
    const float* v_first = (const float*)d_in[2];
    const float* cosb    = (const float*)d_in[3];
    const float* sinb    = (const float*)d_in[4];
    const float* w0      = (const float*)d_in[5];
    const float* w1      = (const float*)d_in[6];
    const float* w2      = (const float*)d_in[7];
    const float* a0      = (const float*)d_in[8];
    const float* a1      = (const float*)d_in[9];
    const float* a2      = (const float*)d_in[10];
    const float* v0      = (const float*)d_in[11];
    const float* v1      = (const float*)d_in[12];
    const float* v2      = (const float*)d_in[13];
    const float* g1      = (const float*)d_in[14];
    const float* g2      = (const float*)d_in[15];
    const float* k_k     = (const float*)d_in[16];
    const float* k_a     = (const float*)d_in[17];
    const float* r_k     = (const float*)d_in[18];
    const float* q_w     = (const float*)d_in[19];
    const float* q_b     = (const float*)d_in[20];
    const float* k_w     = (const float*)d_in[21];
    const float* k_b     = (const float*)d_in[22];
    const float* v_w     = (const float*)d_in[23];
    const float* v_b     = (const float*)d_in[24];
    const float* o_w     = (const float*)d_in[25];
    const float* ln_w    = (const float*)d_in[26];
    const float* ln_b    = (const float*)d_in[27];

    float* out   = (float*)d_out;
    float* s_out = out + (size_t)Tn*Cn;
    float* vf_out = s_out + 32*64*64;

    float *p_bigB, *p_bigBias, *p_B2, *p_h1act, *p_qkvh, *p_wdec, *p_iclr, *p_vsig, *p_gate;
    float *p_rrot, *p_kfin, *p_vfin, *p_kk, *p_y, *p_z;
    cudaGetSymbolAddress((void**)&p_bigB, g_bigB);
    cudaGetSymbolAddress((void**)&p_bigBias, g_bigBias);
    cudaGetSymbolAddress((void**)&p_B2, g_B2);
    cudaGetSymbolAddress((void**)&p_h1act, g_h1act);
    cudaGetSymbolAddress((void**)&p_qkvh, g_qkvh);
    cudaGetSymbolAddress((void**)&p_wdec, g_wdec);
    cudaGetSymbolAddress((void**)&p_iclr, g_iclr);
    cudaGetSymbolAddress((void**)&p_vsig, g_vsig);
    cudaGetSymbolAddress((void**)&p_gate, g_gate);
    cudaGetSymbolAddress((void**)&p_rrot, g_rrot);
    cudaGetSymbolAddress((void**)&p_kfin, g_kfin);
    cudaGetSymbolAddress((void**)&p_vfin, g_vfin);
    cudaGetSymbolAddress((void**)&p_kk, g_kk);
    cudaGetSymbolAddress((void**)&p_y, g_y);
    cudaGetSymbolAddress((void**)&p_z, g_z);

    pack_B<<<Nfused,512>>>(q_w, k_w, v_w, w1, a1, v1, g1, q_b, k_b, v_b,
                           p_bigB, p_bigBias);
    pack_T2<<<dim3(2048,4),256>>>(w2, a2, v2, g2, p_B2);
    gemm_nt_tf32<<<dim3(28,16),256>>>(x, Cn, p_bigB, p_bigBias, p_qkvh, Nfused, Cn, 0);
    h1act_kernel<<<2048,384>>>(p_qkvh, p_h1act);
    gemm_nt_tf32<<<dim3(16,16),256>>>(p_h1act,          384,    p_B2+OFF_W, w0,      p_wdec, Cn,  96, 4);
    gemm_nt_tf32<<<dim3(16,16),256>>>(p_qkvh+3072+96,   Nfused, p_B2+OFF_A, a0,      p_iclr, Cn,  96, 3);
    gemm_nt_tf32<<<dim3(16,16),256>>>(p_qkvh+3072+192,  Nfused, p_B2+OFF_V, v0,      p_vsig, Cn,  64, 3);
    gemm_nt_tf32<<<dim3(16,16),256>>>(p_h1act+96,       384,    p_B2+OFF_G, nullptr, p_gate, Cn, 256, 0);
    prep_kernel<<<8192,256>>>(p_qkvh, p_iclr, p_vsig, v_first, cosb, sinb,
                              k_k, k_a, p_rrot, p_kk, p_kfin, p_vfin);
    scan_kernel<<<128,128>>>(p_wdec, p_kk, p_iclr, p_kfin, p_vfin, p_rrot,
                             wkv_in, p_y, s_out);
    post_kernel<<<8192,256>>>(p_y, p_rrot, p_kfin, p_vfin, p_gate, r_k, ln_w, ln_b, p_z);
    gemm_nt_tf32<<<dim3(16,16),256>>>(p_z, Cn, o_w, nullptr, out, Cn, Cn, 0);
    cudaMemcpyAsync(vf_out, v_first, (size_t)Tn*Cn*sizeof(float),
                    cudaMemcpyDeviceToDevice, 0);
}

// round 8
// speedup vs baseline: 2.3823x; 1.1937x over previous
#include <cuda_runtime.h>
#include <cuda_bf16.h>
#include <math.h>

#define Tn   2048
#define Cn   2048
#define Nfused 3584

#define OFF_W 0
#define OFF_A (2048*96)
#define OFF_V (OFF_A + 2048*96)
#define OFF_G (OFF_V + 2048*64)

// scratch (device globals zero-initialized; scanned streams padded +8 rows)
__device__ float g_bigB[Nfused*Cn];
__device__ float g_bigBias[Nfused];
__device__ float g_B2[2048*512];
__device__ float g_h1act[Tn*512];
__device__ float g_xc[Tn*Cn];
__device__ float g_owc[Cn*Cn];
__device__ float g_qkvh[Tn*Nfused];
__device__ float g_wdec[(Tn+8)*Cn];
__device__ float g_iclr[Tn*Cn];
__device__ float g_ab  [(Tn+8)*Cn];
__device__ float g_vsig[Tn*Cn];
__device__ float g_gate[Tn*Cn];
__device__ float g_rrot[(Tn+8)*Cn];
__device__ float g_kfin[(Tn+8)*Cn];
__device__ float g_vfin[(Tn+8)*Cn];
__device__ float g_kk  [(Tn+8)*Cn];
__device__ float g_y[Tn*Cn];
__device__ float g_z[Tn*Cn];

__device__ __forceinline__ float sigf(float x){ return 1.0f/(1.0f + expf(-x)); }
__device__ __forceinline__ float decay_fn(float v){
    float nv = -v;
    float sp = (nv > 20.0f) ? nv : log1pf(expf(nv));
    return expf(-expf(-sp - 0.5f));
}
__device__ __forceinline__ float f2tf32f(float f){
    unsigned u;
    asm("cvt.rna.tf32.f32 %0, %1;" : "=r"(u) : "f"(f));
    return __uint_as_float(u);
}

#define CP16(sm, gp) asm volatile("cp.async.cg.shared.global [%0], [%1], 16;\n" :: "r"(sm), "l"(gp) : "memory")
#define CPCOMMIT()   asm volatile("cp.async.commit_group;\n" ::)
#define CPWAIT(n)    asm volatile("cp.async.wait_group %0;\n" :: "n"(n) : "memory")

__device__ __forceinline__ int SW(int row, int col){
    return row*16 + (col ^ (4*((row>>1)&3)));
}

// ---------------- pipelined TF32 GEMM body (operands pre-truncated to tf32) ----------------
// epi: 0 none, 3 sigmoid(c+bias), 4 decay(c+bias)
__device__ __forceinline__ void gemm_body(
    const float* __restrict__ A, int lda, const float* __restrict__ B,
    const float* __restrict__ bias, float* __restrict__ C, int N, int K, int epi)
{
    __shared__ float As[3][128*16];
    __shared__ float Bs[3][128*16];
    const int m0 = blockIdx.y*128, n0 = blockIdx.x*128;
    const int tid = threadIdx.x;
    const int wid = tid>>5, lane = tid&31;
    const int wm = (wid>>1)*32, wn = (wid&1)*64;
    const int r = lane>>2, q = lane&3;

    const int row0 = tid>>2, c40 = (tid&3)*4;
    const int row1 = row0 + 64;
    const float* Ag = A + (size_t)m0*lda;
    const float* Bg = B + (size_t)n0*K;
    const size_t a0off = (size_t)row0*lda + c40;
    const size_t a1off = (size_t)row1*lda + c40;
    const size_t b0off = (size_t)row0*K + c40;
    const size_t b1off = (size_t)row1*K + c40;

    float acc[2][8][4];
    #pragma unroll
    for (int i=0;i<2;i++)
        #pragma unroll
        for (int j=0;j<8;j++)
            #pragma unroll
            for (int c=0;c<4;c++) acc[i][j][c]=0.f;

    const int niter = K/16;
    #pragma unroll
    for (int p=0;p<2;p++){
        unsigned sa = (unsigned)__cvta_generic_to_shared(&As[p][0]);
        unsigned sb = (unsigned)__cvta_generic_to_shared(&Bs[p][0]);
        CP16(sa + SW(row0,c40)*4, Ag + p*16 + a0off);
        CP16(sa + SW(row1,c40)*4, Ag + p*16 + a1off);
        CP16(sb + SW(row0,c40)*4, Bg + p*16 + b0off);
        CP16(sb + SW(row1,c40)*4, Bg + p*16 + b1off);
        CPCOMMIT();
    }

    for (int it=0; it<niter; it++){
        const int nx = it+2;
        if (nx < niter){
            const int buf = nx%3;
            unsigned sa = (unsigned)__cvta_generic_to_shared(&As[buf][0]);
            unsigned sb = (unsigned)__cvta_generic_to_shared(&Bs[buf][0]);
            CP16(sa + SW(row0,c40)*4, Ag + nx*16 + a0off);
            CP16(sa + SW(row1,c40)*4, Ag + nx*16 + a1off);
            CP16(sb + SW(row0,c40)*4, Bg + nx*16 + b0off);
            CP16(sb + SW(row1,c40)*4, Bg + nx*16 + b1off);
        }
        CPCOMMIT();
        CPWAIT(2);
        __syncthreads();
        const float* as = As[it%3];
        const float* bs = Bs[it%3];
        #pragma unroll
        for (int ks=0; ks<2; ks++){
            const int kk = ks*8;
            unsigned a[2][4], b[8][2];
            #pragma unroll
            for (int mt=0;mt<2;mt++){
                const int row = wm + mt*16;
                a[mt][0]=__float_as_uint(as[SW(row+r,  kk+q  )]);
                a[mt][1]=__float_as_uint(as[SW(row+r+8,kk+q  )]);
                a[mt][2]=__float_as_uint(as[SW(row+r,  kk+q+4)]);
                a[mt][3]=__float_as_uint(as[SW(row+r+8,kk+q+4)]);
            }
            #pragma unroll
            for (int nt=0;nt<8;nt++){
                const int col = wn + nt*8;
                b[nt][0]=__float_as_uint(bs[SW(col+r, kk+q  )]);
                b[nt][1]=__float_as_uint(bs[SW(col+r, kk+q+4)]);
            }
            #pragma unroll
            for (int mt=0;mt<2;mt++){
                #pragma unroll
                for (int nt=0;nt<8;nt++){
                    asm volatile(
                        "mma.sync.aligned.m16n8k8.row.col.f32.tf32.tf32.f32 "
                        "{%0,%1,%2,%3}, {%4,%5,%6,%7}, {%8,%9}, {%0,%1,%2,%3};"
                        : "+f"(acc[mt][nt][0]),"+f"(acc[mt][nt][1]),
                          "+f"(acc[mt][nt][2]),"+f"(acc[mt][nt][3])
                        : "r"(a[mt][0]),"r"(a[mt][1]),"r"(a[mt][2]),"r"(a[mt][3]),
                          "r"(b[nt][0]),"r"(b[nt][1]));
                }
            }
        }
        __syncthreads();
    }
    #pragma unroll
    for (int mt=0;mt<2;mt++){
        #pragma unroll
        for (int nt=0;nt<8;nt++){
            int row = m0 + wm + mt*16 + r;
            int col = n0 + wn + nt*8 + q*2;
            float bx=0.f, by=0.f;
            if (bias){ bx=bias[col]; by=bias[col+1]; }
            float o00=acc[mt][nt][0]+bx, o01=acc[mt][nt][1]+by;
            float o10=acc[mt][nt][2]+bx, o11=acc[mt][nt][3]+by;
            if (epi==3){ o00=sigf(o00); o01=sigf(o01); o10=sigf(o10); o11=sigf(o11); }
            else if (epi==4){ o00=decay_fn(o00); o01=decay_fn(o01); o10=decay_fn(o10); o11=decay_fn(o11); }
            *(float2*)(C + (size_t)row*N + col)     = make_float2(o00,o01);
            *(float2*)(C + (size_t)(row+8)*N + col) = make_float2(o10,o11);
        }
    }
}

__global__ __launch_bounds__(256) void gemm_nt_tf32(
    const float* __restrict__ A, int lda, const float* __restrict__ B,
    const float* __restrict__ bias, float* __restrict__ C, int N, int K, int epi)
{
    gemm_body(A, lda, B, bias, C, N, K, epi);
}

// batched stage-2 LoRA GEMMs (blockIdx.z selects)
__global__ __launch_bounds__(256) void gemm_stage2(
    const float* __restrict__ h1, const float* __restrict__ B2,
    const float* __restrict__ w0, const float* __restrict__ a0,
    const float* __restrict__ v0,
    float* __restrict__ wdec, float* __restrict__ iclr,
    float* __restrict__ vsig, float* __restrict__ gate)
{
    const int z = blockIdx.z;
    if (z==0)      gemm_body(h1+0,   512, B2+OFF_W, w0,      wdec, Cn,  96, 4);
    else if (z==1) gemm_body(h1+96,  512, B2+OFF_A, a0,      iclr, Cn,  96, 3);
    else if (z==2) gemm_body(h1+192, 512, B2+OFF_V, v0,      vsig, Cn,  64, 3);
    else           gemm_body(h1+256, 512, B2+OFF_G, nullptr, gate, Cn, 256, 0);
}

// cvt-copy: y=0 -> x, y=1 -> o_w  (pre-truncate to tf32)
__global__ void cvt_copy(const float* __restrict__ x, const float* __restrict__ ow,
                         float* __restrict__ xc, float* __restrict__ owc)
{
    const float* src = blockIdx.y ? ow : x;
    float* dst = blockIdx.y ? owc : xc;
    size_t idx = ((size_t)blockIdx.x*1024 + threadIdx.x)*4;
    float4 v = *(const float4*)(src + idx);
    v.x=f2tf32f(v.x); v.y=f2tf32f(v.y); v.z=f2tf32f(v.z); v.w=f2tf32f(v.w);
    *(float4*)(dst + idx) = v;
}

// pack fused B = [q_w ; k_w ; v_w ; wcatT] rows (tf32-truncated), and fused bias
__global__ void pack_B(const float* __restrict__ q_w, const float* __restrict__ k_w,
                       const float* __restrict__ v_w,
                       const float* __restrict__ w1, const float* __restrict__ a1,
                       const float* __restrict__ v1, const float* __restrict__ g1,
                       const float* __restrict__ q_b, const float* __restrict__ k_b,
                       const float* __restrict__ v_b,
                       float* __restrict__ Bout, float* __restrict__ biasOut)
{
    int row = blockIdx.x;
    for (int col = threadIdx.x; col < Cn; col += blockDim.x){
        float v;
        if (row < 2048)       v = q_w[(size_t)row*Cn + col];
        else if (row < 2560)  v = k_w[(size_t)(row-2048)*Cn + col];
        else if (row < 3072)  v = v_w[(size_t)(row-2560)*Cn + col];
        else {
            int c = row - 3072;
            if      (c < 96)  v = w1[(size_t)col*96  + c];
            else if (c < 192) v = a1[(size_t)col*96  + (c-96)];
            else if (c < 256) v = v1[(size_t)col*64  + (c-192)];
            else              v = g1[(size_t)col*256 + (c-256)];
        }
        Bout[(size_t)row*Cn + col] = f2tf32f(v);
    }
    if (threadIdx.x == 0){
        float bv = 0.f;
        if (row < 2048)      bv = q_b[row];
        else if (row < 2560) bv = k_b[row-2048];
        else if (row < 3072) bv = v_b[row-2560];
        biasOut[row] = bv;
    }
}

// transpose-pack stage-2 weights (tf32-truncated)
__global__ void pack_T2(const float* __restrict__ w2, const float* __restrict__ a2,
                        const float* __restrict__ v2, const float* __restrict__ g2,
                        float* __restrict__ out)
{
    int n = blockIdx.x, which = blockIdx.y, k = threadIdx.x;
    if (which==0){ if (k<96)  out[OFF_W + (size_t)n*96  + k] = f2tf32f(w2[(size_t)k*Cn + n]); }
    else if (which==1){ if (k<96)  out[OFF_A + (size_t)n*96  + k] = f2tf32f(a2[(size_t)k*Cn + n]); }
    else if (which==2){ if (k<64)  out[OFF_V + (size_t)n*64  + k] = f2tf32f(v2[(size_t)k*Cn + n]); }
    else              { if (k<256) out[OFF_G + (size_t)n*256 + k] = f2tf32f(g2[(size_t)k*Cn + n]); }
}

// pack + activate stage-2 A: [tanh(w)|a|v|sigmoid(g)] widths 96|96|64|256 (tf32-truncated)
__global__ void h1act_kernel(const float* __restrict__ qkvh, float* __restrict__ out)
{
    int row = blockIdx.x, c = threadIdx.x;
    float v = qkvh[(size_t)row*Nfused + 3072 + c];
    if (c < 96)       v = tanhf(v);
    else if (c >= 256) v = sigf(v);
    out[(size_t)row*512 + c] = f2tf32f(v);
}

// rope r/k, GQA repeat, kk normalize, k_final, v_final, ab = kk*iclr
__global__ __launch_bounds__(256) void prep_kernel(
    const float* __restrict__ qkvh,
    const float* __restrict__ iclr, const float* __restrict__ vsig, const float* __restrict__ vfirst,
    const float* __restrict__ cosb, const float* __restrict__ sinb,
    const float* __restrict__ k_k, const float* __restrict__ k_a,
    float* __restrict__ rrot, float* __restrict__ kkout, float* __restrict__ about,
    float* __restrict__ kfin, float* __restrict__ vfin)
{
    int wid = (blockIdx.x*blockDim.x + threadIdx.x) >> 5;
    int l = threadIdx.x & 31;
    int t = wid >> 5, h = wid & 31;
    int d0 = l, d1 = l+32;
    float c0 = cosb[t*64+d0], c1 = cosb[t*64+d1];
    float s0 = sinb[t*64+d0], s1 = sinb[t*64+d1];
    int base = t*Cn + h*64;
    int rbase = t*Nfused + h*64;
    int kbase = t*Nfused + 2048 + (h>>2)*64;
    int vbase = t*Nfused + 2560 + (h>>2)*64;
    float r0 = qkvh[rbase+d0], r1 = qkvh[rbase+d1];
    rrot[base+d0] = r0*c0 - r1*s0;
    rrot[base+d1] = r1*c1 + r0*s1;
    float k0 = qkvh[kbase+d0], k1 = qkvh[kbase+d1];
    float kr0 = k0*c0 - k1*s0, kr1 = k1*c1 + k0*s1;
    float m0 = kr0 * k_k[h*64+d0], m1 = kr1 * k_k[h*64+d1];
    float ss = m0*m0 + m1*m1;
    #pragma unroll
    for (int o=16;o>0;o>>=1) ss += __shfl_xor_sync(0xffffffffu, ss, o);
    float inv = 1.0f / fmaxf(sqrtf(ss), 1e-12f);
    float kk0 = m0*inv, kk1 = m1*inv;
    kkout[base+d0] = kk0; kkout[base+d1] = kk1;
    float ic0 = iclr[base+d0], ic1 = iclr[base+d1];
    about[base+d0] = kk0*ic0; about[base+d1] = kk1*ic1;
    kfin[base+d0] = kr0 * (1.0f + (ic0-1.0f)*k_a[h*64+d0]);
    kfin[base+d1] = kr1 * (1.0f + (ic1-1.0f)*k_a[h*64+d1]);
    float v0v = qkvh[vbase+d0], v1v = qkvh[vbase+d1];
    vfin[base+d0] = v0v + (vfirst[base+d0]-v0v)*vsig[base+d0];
    vfin[base+d1] = v1v + (vfirst[base+d1]-v1v)*vsig[base+d1];
}

// scan v3: direct-S, 2 reductions/step, ring of 5 slots x 2 timesteps
// slot layout (floats): [w(64)|kk(64)|ab(64)|kf(64)|rr(64)|vf(16)] per step, 336/step, 672/slot
__global__ __launch_bounds__(128) void scan_kernel(
    const float* __restrict__ wdec, const float* __restrict__ kkb,
    const float* __restrict__ abb,  const float* __restrict__ kf,
    const float* __restrict__ vf,   const float* __restrict__ rr,
    const float* __restrict__ s_in, float* __restrict__ yout, float* __restrict__ s_out)
{
    __shared__ float ring[5*672];
    const int b = blockIdx.x, h = b >> 2, rbk = b & 3;
    const int tid = threadIdx.x, rl = tid >> 3, sub = tid & 7;
    const int i = rbk*16 + rl, cb = sub*8;
    const int voff = h*64 + i;

    // producer assignment: 80 threads for 5 streams x 16 chunks, 4 for vf
    const float* src = nullptr;
    int dloc = 0;
    if (tid < 80){
        int s = tid >> 4, col16 = (tid & 15)*4;
        const float* bases[5] = {wdec, kkb, abb, kf, rr};
        src = bases[s] + h*64 + col16;
        dloc = s*64 + col16;
    } else if (tid < 84){
        int j = tid - 80;
        src = vf + h*64 + rbk*16 + j*4;
        dloc = 320 + j*4;
    }
    const unsigned smbase = (unsigned)__cvta_generic_to_shared(ring);

    // prologue: fill slots 0..3 (steps 0..7), one commit per slot
    for (int s=0; s<4; s++){
        if (src){
            CP16(smbase + (s*672 +       dloc)*4, src + (size_t)(2*s  )*Cn);
            CP16(smbase + (s*672 + 336 + dloc)*4, src + (size_t)(2*s+1)*Cn);
        }
        CPCOMMIT();
    }

    float S[8];
    {
        const float4* sp = (const float4*)(s_in + (size_t)(h*64 + i)*64 + cb);
        float4 a = sp[0], c = sp[1];
        S[0]=a.x;S[1]=a.y;S[2]=a.z;S[3]=a.w;S[4]=c.x;S[5]=c.y;S[6]=c.z;S[7]=c.w;
    }

    CPWAIT(3);
    __syncthreads();
    float d;
    {
        const float* K0 = ring + 64 + cb;   // kk step 0
        float t0=0.f, t1=0.f;
        #pragma unroll
        for (int q2=0;q2<4;q2++){ t0 = fmaf(S[q2], K0[q2], t0); t1 = fmaf(S[q2+4], K0[q2+4], t1); }
        d = t0 + t1;
        d += __shfl_xor_sync(0xffffffffu, d, 1);
        d += __shfl_xor_sync(0xffffffffu, d, 2);
        d += __shfl_xor_sync(0xffffffffu, d, 4);
    }

    for (int j=0; j<Tn/2; j++){
        CPWAIT(2);                 // slots j, j+1 complete
        __syncthreads();           // iter j-1 reads done -> safe to overwrite slot j-1 (= j+4 mod 5)
        {
            const int ws = ((j+4)%5)*672;
            if (src){
                CP16(smbase + (ws +       dloc)*4, src + (size_t)(2*j+8)*Cn);
                CP16(smbase + (ws + 336 + dloc)*4, src + (size_t)(2*j+9)*Cn);
            }
            CPCOMMIT();
        }
        const int s0 = (j%5)*672, s1 = ((j+1)%5)*672;
        #pragma unroll
        for (int d2=0; d2<2; d2++){
            const float* P  = ring + s0 + d2*336;
            const float* Kn = ring + (d2==0 ? (s0 + 336 + 64) : (s1 + 64)) + cb;
            float4 w0=((const float4*)(P+  0+cb))[0], w1=((const float4*)(P+  0+cb))[1];
            float4 a0=((const float4*)(P+128+cb))[0], a1=((const float4*)(P+128+cb))[1];
            float4 f0=((const float4*)(P+192+cb))[0], f1=((const float4*)(P+192+cb))[1];
            float4 r0=((const float4*)(P+256+cb))[0], r1=((const float4*)(P+256+cb))[1];
            float4 n0=((const float4*)Kn)[0],         n1=((const float4*)Kn)[1];
            const float vi = P[320 + rl];
            float w[8]={w0.x,w0.y,w0.z,w0.w,w1.x,w1.y,w1.z,w1.w};
            float ab[8]={a0.x,a0.y,a0.z,a0.w,a1.x,a1.y,a1.z,a1.w};
            float fv[8]={f0.x,f0.y,f0.z,f0.w,f1.x,f1.y,f1.z,f1.w};
            float rv[8]={r0.x,r0.y,r0.z,r0.w,r1.x,r1.y,r1.z,r1.w};
            float kn[8]={n0.x,n0.y,n0.z,n0.w,n1.x,n1.y,n1.z,n1.w};

            float dn0=0.f,dn1=0.f,y0=0.f,y1=0.f;
            #pragma unroll
            for (int q2=0;q2<8;q2++){
                float un = fmaf(S[q2], w[q2], vi*fv[q2]);
                S[q2] = fmaf(-d, ab[q2], un);
                if (q2<4){ dn0 = fmaf(S[q2], kn[q2], dn0); y0 = fmaf(S[q2], rv[q2], y0); }
                else     { dn1 = fmaf(S[q2], kn[q2], dn1); y1 = fmaf(S[q2], rv[q2], y1); }
            }
            float dn = dn0+dn1, yv = y0+y1;
            dn += __shfl_xor_sync(0xffffffffu, dn, 1);
            yv += __shfl_xor_sync(0xffffffffu, yv, 1);
            dn += __shfl_xor_sync(0xffffffffu, dn, 2);
            yv += __shfl_xor_sync(0xffffffffu, yv, 2);
            dn += __shfl_xor_sync(0xffffffffu, dn, 4);
            yv += __shfl_xor_sync(0xffffffffu, yv, 4);
            if (sub==0) yout[(size_t)(2*j+d2)*Cn + voff] = yv;
            d = dn;
        }
    }
    float4* so = (float4*)(s_out + (size_t)(h*64+i)*64 + cb);
    so[0] = make_float4(S[0],S[1],S[2],S[3]);
    so[1] = make_float4(S[4],S[5],S[6],S[7]);
}

// groupnorm + ln + bonus + gate (z written tf32-truncated for o-GEMM)
__global__ __launch_bounds__(256) void post_kernel(
    const float* __restrict__ y, const float* __restrict__ rrot,
    const float* __restrict__ kfin, const float* __restrict__ vfin,
    const float* __restrict__ gate, const float* __restrict__ r_k,
    const float* __restrict__ ln_w, const float* __restrict__ ln_b,
    float* __restrict__ z)
{
    int wid = (blockIdx.x*blockDim.x + threadIdx.x) >> 5;
    int l = threadIdx.x & 31;
    int t = wid >> 5, h = wid & 31;
    int base = t*Cn + h*64;
    int d0 = l, d1 = l+32;
    float y0 = y[base+d0], y1 = y[base+d1];
    float s = y0+y1, sq = y0*y0 + y1*y1;
    float r0 = rrot[base+d0], r1 = rrot[base+d1];
    float dot = r0*kfin[base+d0]*r_k[h*64+d0] + r1*kfin[base+d1]*r_k[h*64+d1];
    #pragma unroll
    for (int o=16;o>0;o>>=1){
        s   += __shfl_xor_sync(0xffffffffu, s, o);
        sq  += __shfl_xor_sync(0xffffffffu, sq, o);
        dot += __shfl_xor_sync(0xffffffffu, dot, o);
    }
    float mu = s * (1.0f/64.0f);
    float var = sq * (1.0f/64.0f) - mu*mu;
    float rstd = rsqrtf(var + 6.4e-4f);
    float n0 = (y0-mu)*rstd*ln_w[h*64+d0] + ln_b[h*64+d0];
    float n1 = (y1-mu)*rstd*ln_w[h*64+d1] + ln_b[h*64+d1];
    z[base+d0] = f2tf32f((n0 + dot*vfin[base+d0]) * gate[base+d0]);
    z[base+d1] = f2tf32f((n1 + dot*vfin[base+d1]) * gate[base+d1]);
}

extern "C" void kernel_launch(void* const* d_in, const int* in_sizes, int n_in,
                              void* d_out, int out_size) {
    const float* x       = (const float*)d_in[0];
    const float* wkv_in  = (const float*)d_in[1];
    const float* v_first = (const float*)d_in[2];
    const float* cosb    = (const float*)d_in[3];
    const float* sinb    = (const float*)d_in[4];
    const float* w0      = (const float*)d_in[5];
    const float* w1      = (const float*)d_in[6];
    const float* w2      = (const float*)d_in[7];
    const float* a0      = (const float*)d_in[8];
    const float* a1      = (const float*)d_in[9];
    const float* a2      = (const float*)d_in[10];
    const float* v0      = (const float*)d_in[11];
    const float* v1      = (const float*)d_in[12];
    const float* v2      = (const float*)d_in[13];
    const float* g1      = (const float*)d_in[14];
    const float* g2      = (const float*)d_in[15];
    const float* k_k     = (const float*)d_in[16];
    const float* k_a     = (const float*)d_in[17];
    const float* r_k     = (const float*)d_in[18];
    const float* q_w     = (const float*)d_in[19];
    const float* q_b     = (const float*)d_in[20];
    const float* k_w     = (const float*)d_in[21];
    const float* k_b     = (const float*)d_in[22];
    const float* v_w     = (const float*)d_in[23];
    const float* v_b     = (const float*)d_in[24];
    const float* o_w     = (const float*)d_in[25];
    const float* ln_w    = (const float*)d_in[26];
    const float* ln_b    = (const float*)d_in[27];

    float* out   = (float*)d_out;
    float* s_out = out + (size_t)Tn*Cn;
    float* vf_out = s_out + 32*64*64;

    float *p_bigB, *p_bigBias, *p_B2, *p_h1act, *p_xc, *p_owc, *p_qkvh;
    float *p_wdec, *p_iclr, *p_ab, *p_vsig, *p_gate;
    float *p_rrot, *p_kfin, *p_vfin, *p_kk, *p_y, *p_z;
    cudaGetSymbolAddress((void**)&p_bigB, g_bigB);
    cudaGetSymbolAddress((void**)&p_bigBias, g_bigBias);
    cudaGetSymbolAddress((void**)&p_B2, g_B2);
    cudaGetSymbolAddress((void**)&p_h1act, g_h1act);
    cudaGetSymbolAddress((void**)&p_xc, g_xc);
    cudaGetSymbolAddress((void**)&p_owc, g_owc);
    cudaGetSymbolAddress((void**)&p_qkvh, g_qkvh);
    cudaGetSymbolAddress((void**)&p_wdec, g_wdec);
    cudaGetSymbolAddress((void**)&p_iclr, g_iclr);
    cudaGetSymbolAddress((void**)&p_ab, g_ab);
    cudaGetSymbolAddress((void**)&p_vsig, g_vsig);
    cudaGetSymbolAddress((void**)&p_gate, g_gate);
    cudaGetSymbolAddress((void**)&p_rrot, g_rrot);
    cudaGetSymbolAddress((void**)&p_kfin, g_kfin);
    cudaGetSymbolAddress((void**)&p_vfin, g_vfin);
    cudaGetSymbolAddress((void**)&p_kk, g_kk);
    cudaGetSymbolAddress((void**)&p_y, g_y);
    cudaGetSymbolAddress((void**)&p_z, g_z);

    cvt_copy<<<dim3(1024,2),1024>>>(x, o_w, p_xc, p_owc);
    pack_B<<<Nfused,512>>>(q_w, k_w, v_w, w1, a1, v1, g1, q_b, k_b, v_b,
                           p_bigB, p_bigBias);
    pack_T2<<<dim3(2048,4),256>>>(w2, a2, v2, g2, p_B2);
    gemm_nt_tf32<<<dim3(28,16),256>>>(p_xc, Cn, p_bigB, p_bigBias, p_qkvh, Nfused, Cn, 0);
    h1act_kernel<<<2048,512>>>(p_qkvh, p_h1act);
    gemm_stage2<<<dim3(16,16,4),256>>>(p_h1act, p_B2, w0, a0, v0,
                                       p_wdec, p_iclr, p_vsig, p_gate);
    prep_kernel<<<8192,256>>>(p_qkvh, p_iclr, p_vsig, v_first, cosb, sinb,
                              k_k, k_a, p_rrot, p_kk, p_ab, p_kfin, p_vfin);
    scan_kernel<<<128,128>>>(p_wdec, p_kk, p_ab, p_kfin, p_vfin, p_rrot,
                             wkv_in, p_y, s_out);
    post_kernel<<<8192,256>>>(p_y, p_rrot, p_kfin, p_vfin, p_gate, r_k, ln_w, ln_b, p_z);
    gemm_nt_tf32<<<dim3(16,16),256>>>(p_z, Cn, p_owc, nullptr, out, Cn, Cn, 0);
    cudaMemcpyAsync(vf_out, v_first, (size_t)Tn*Cn*sizeof(float),
                    cudaMemcpyDeviceToDevice, 0);
}